// round 7
// baseline (speedup 1.0000x reference)
#include <cuda_runtime.h>
#include <cuda_bf16.h>
#include <math.h>
#include <stdint.h>

#define BB   512
#define FF   1024
#define HIST 20
#define FUT  30
#define NL   3

#define TM   128
#define KC   64
#define NCH  32
#define NSTG 3

#define SMEM_STAGE 65536
#define OFF_BIAS   (NSTG*SMEM_STAGE + 64)
#define SMEM_REQ   (OFF_BIAS + 512 + 1024)

// ---------------- device globals ---------------------------------------------
// Weights hi/lo pre-swizzled into SMEM tile layout, 16KB blocks:
// block ((l*32 + nt)*32 + kc)*2 + plane.  Column j = 16u + 8*(g>=2) + 2c + (g&1)
// where f_local = 4u + c  (all 4 gates of an f share one mma lane).
__device__ __nv_bfloat16 g_W[(size_t)3*32*32*2*8192];
__device__ __nv_bfloat16 g_xhi[HIST][BB*FF];
__device__ __nv_bfloat16 g_xlo[HIST][BB*FF];
__device__ __nv_bfloat16 g_hhi[2][NL][BB*FF];
__device__ __nv_bfloat16 g_hlo[2][NL][BB*FF];
__device__ float         g_c[NL][BB*FF];
__device__ __nv_bfloat16 g_cinhi[BB*FF];
__device__ __nv_bfloat16 g_cinlo[BB*FF];

// ---------------- helpers ----------------------------------------------------
#define CP16(dst, src) \
    asm volatile("cp.async.ca.shared.global [%0], [%1], 16;" \
        :: "r"((uint32_t)(dst)), "l"(src) : "memory")

__device__ __forceinline__ void ldsm4(uint32_t& r0, uint32_t& r1,
                                      uint32_t& r2, uint32_t& r3, uint32_t addr) {
    asm volatile("ldmatrix.sync.aligned.m8n8.x4.shared.b16 {%0,%1,%2,%3}, [%4];"
                 : "=r"(r0), "=r"(r1), "=r"(r2), "=r"(r3) : "r"(addr));
}
__device__ __forceinline__ void mma16816(float* c, const uint32_t* a,
                                         const uint32_t* b) {
    asm volatile("mma.sync.aligned.m16n8k16.row.col.f32.bf16.bf16.f32 "
        "{%0,%1,%2,%3}, {%4,%5,%6,%7}, {%8,%9}, {%0,%1,%2,%3};"
        : "+f"(c[0]), "+f"(c[1]), "+f"(c[2]), "+f"(c[3])
        : "r"(a[0]), "r"(a[1]), "r"(a[2]), "r"(a[3]), "r"(b[0]), "r"(b[1]));
}

// ---------------- prep kernels -----------------------------------------------
__global__ void prep_weights(const float* __restrict__ Wih,
                             const float* __restrict__ Whh) {
    long i = (long)blockIdx.x * blockDim.x + threadIdx.x;
    if (i >= 3L*4096*2048) return;
    int  k     = (int)(i & 2047);
    long r     = i >> 11;
    int  row_w = (int)(r & 4095);
    int  l     = (int)(r >> 12);
    float w = (k < 1024)
        ? Wih[(long)l*4096*1024 + (long)row_w*1024 + k]
        : Whh[(long)l*4096*1024 + (long)row_w*1024 + (k-1024)];
    __nv_bfloat16 hi = __float2bfloat16(w);
    __nv_bfloat16 lo = __float2bfloat16(w - __bfloat162float(hi));
    int g = row_w >> 10, f = row_w & 1023;
    int nt = f >> 5, fl = f & 31;
    int j = ((fl >> 2) << 4) | ((g >> 1) << 3) | ((fl & 3) << 1) | (g & 1);
    int kc = k >> 6, kl = k & 63;
    int off = j*128 + kl*2;
    off ^= (off >> 3) & 0x70;
    long blk = (((long)l*32 + nt)*32 + kc)*2;
    g_W[(blk + 0)*8192 + (off >> 1)] = hi;
    g_W[(blk + 1)*8192 + (off >> 1)] = lo;
}

__global__ void prep_x(const float* __restrict__ seq) {
    int i = blockIdx.x * blockDim.x + threadIdx.x;
    if (i >= BB*FF) return;
    const float* s = seq + (size_t)i * HIST;
    #pragma unroll
    for (int t = 0; t < HIST; t++) {
        float v = s[t];
        __nv_bfloat16 hi = __float2bfloat16(v);
        g_xhi[t][i] = hi;
        g_xlo[t][i] = __float2bfloat16(v - __bfloat162float(hi));
    }
}

__global__ void zero_state() {
    int i = blockIdx.x * blockDim.x + threadIdx.x;
    if (i < 2*NL*BB*FF) {
        ((unsigned short*)g_hhi)[i] = 0;
        ((unsigned short*)g_hlo)[i] = 0;
    }
    if (i < NL*BB*FF) ((float*)g_c)[i] = 0.0f;
}

__global__ void prep_cin() {
    int i = blockIdx.x * blockDim.x + threadIdx.x;
    if (i >= BB*FF) return;
    float v = g_c[NL-1][i];
    __nv_bfloat16 hi = __float2bfloat16(v);
    g_cinhi[i] = hi;
    g_cinlo[i] = __float2bfloat16(v - __bfloat162float(hi));
}

// ---------------- chunk loader (512 threads) ----------------------------------
__device__ __forceinline__ void load_chunk(uint32_t stage, int kc,
    const __nv_bfloat16* Xhi, const __nv_bfloat16* Xlo,
    const __nv_bfloat16* Hhi, const __nv_bfloat16* Hlo,
    const __nv_bfloat16* Wnt, int m0, int t)
{
    const __nv_bfloat16 *phi, *plo; int kb;
    if (kc < 16) { phi = Xhi; plo = Xlo; kb = kc * KC; }
    else         { phi = Hhi; plo = Hlo; kb = (kc-16) * KC; }
    const uint32_t Ahi = stage, Alo = stage + 16384;
    const uint32_t Bhi = stage + 32768, Blo = stage + 49152;
    const int ku = t & 7, rb = t >> 3;           // rb 0..63
    #pragma unroll
    for (int p = 0; p < 2; p++) {
        int row = p*64 + rb;
        int ob  = row*128 + ku*16;
        int swo = ob ^ ((ob >> 3) & 0x70);
        size_t sidx = (size_t)(m0 + row)*FF + kb + ku*8;
        CP16(Ahi + swo, phi + sidx);
        CP16(Alo + swo, plo + sidx);
    }
    const char* wb = (const char*)(Wnt + (size_t)kc*2*8192);
    #pragma unroll
    for (int p = 0; p < 2; p++) {
        int off = p*8192 + t*16;
        CP16(Bhi + off, wb + off);
        CP16(Blo + off, wb + 16384 + off);
    }
}

// ---------------- fused LSTM cell (16 warps, HMMA) ----------------------------
extern __shared__ char dsm[];

__global__ __launch_bounds__(512, 1)
void lstm_cell(const __nv_bfloat16* __restrict__ Xhi,
               const __nv_bfloat16* __restrict__ Xlo,
               const __nv_bfloat16* __restrict__ Hhi,
               const __nv_bfloat16* __restrict__ Hlo,
               __nv_bfloat16* __restrict__ HWhi,
               __nv_bfloat16* __restrict__ HWlo,
               float* __restrict__ C,
               const __nv_bfloat16* __restrict__ Wlay,
               const float* __restrict__ bih,
               const float* __restrict__ bhh,
               float* __restrict__ out, int out_t)
{
    char* base = (char*)(((uintptr_t)dsm + 1023) & ~(uintptr_t)1023);
    uint32_t sb;
    asm("{ .reg .u64 tmp; cvta.to.shared.u64 tmp, %1; cvt.u32.u64 %0, tmp; }"
        : "=r"(sb) : "l"(base));

    const int t    = threadIdx.x;
    const int w    = t >> 5;
    const int lane = t & 31;
    const int nt   = blockIdx.x;
    const int m0   = blockIdx.y * TM;
    const int f0   = nt * 32;
    float* bias_s  = (float*)(base + OFF_BIAS);

    if (t < 128) {   // bias_s[j]: decode j -> (f, g)
        int u = t >> 4, g = ((t >> 3) & 1)*2 + (t & 1), c = (t >> 1) & 3;
        int f = f0 + 4*u + c;
        bias_s[t] = bih[g*FF + f] + bhh[g*FF + f];
    }

    const __nv_bfloat16* Wnt = Wlay + (size_t)nt * (32*2*8192);

    // warp tiling: w_m = rows (w&3)*32, w_n = j-cols (w>>2)*32 (4 n8-tiles)
    const int w_m    = w & 3;
    const int w_n    = w >> 2;
    const int rbaseA = w_m * 32;
    const int ntb    = w_n * 4;
    const int a_ro   = (lane & 7) + ((lane >> 3) & 1)*8;
    const int a_bh   = (lane >> 4) * 16;
    const int b_jo   = lane & 7;
    const int b_bh   = ((lane >> 3) & 1) * 16;
    const int b_ts   = lane >> 4;

    float acc[2][4][4];
    #pragma unroll
    for (int a = 0; a < 2; a++)
        #pragma unroll
        for (int b = 0; b < 4; b++)
            #pragma unroll
            for (int c = 0; c < 4; c++) acc[a][b][c] = 0.0f;

    // prologue: distance-2 prefetch
    load_chunk(sb + 0*SMEM_STAGE, 0, Xhi, Xlo, Hhi, Hlo, Wnt, m0, t);
    asm volatile("cp.async.commit_group;" ::: "memory");
    load_chunk(sb + 1*SMEM_STAGE, 1, Xhi, Xlo, Hhi, Hlo, Wnt, m0, t);
    asm volatile("cp.async.commit_group;" ::: "memory");

    for (int kc = 0; kc < NCH; kc++) {
        if (kc + 1 < NCH) asm volatile("cp.async.wait_group 1;" ::: "memory");
        else              asm volatile("cp.async.wait_group 0;" ::: "memory");
        __syncthreads();

        if (kc + 2 < NCH) {
            load_chunk(sb + ((kc+2) % NSTG)*SMEM_STAGE, kc + 2,
                       Xhi, Xlo, Hhi, Hlo, Wnt, m0, t);
            asm volatile("cp.async.commit_group;" ::: "memory");
        }

        const uint32_t stage = sb + (kc % NSTG)*SMEM_STAGE;
        const uint32_t Ahi = stage, Alo = stage + 16384;
        const uint32_t Bhi = stage + 32768, Blo = stage + 49152;

        #pragma unroll
        for (int s16 = 0; s16 < 4; s16++) {
            uint32_t aH[2][4], aL[2][4], bH[4][2], bL[4][2];
            const int abyte = s16*32 + a_bh;
            #pragma unroll
            for (int mt = 0; mt < 2; mt++) {
                int row = rbaseA + mt*16 + a_ro;
                int ob  = row*128 + abyte;
                int swo = ob ^ ((ob >> 3) & 0x70);
                ldsm4(aH[mt][0], aH[mt][1], aH[mt][2], aH[mt][3], Ahi + swo);
                ldsm4(aL[mt][0], aL[mt][1], aL[mt][2], aL[mt][3], Alo + swo);
            }
            const int bbyte = s16*32 + b_bh;
            #pragma unroll
            for (int pp = 0; pp < 2; pp++) {
                int j  = (ntb + 2*pp + b_ts)*8 + b_jo;
                int ob = j*128 + bbyte;
                int swo = ob ^ ((ob >> 3) & 0x70);
                ldsm4(bH[2*pp][0], bH[2*pp][1], bH[2*pp+1][0], bH[2*pp+1][1], Bhi + swo);
                ldsm4(bL[2*pp][0], bL[2*pp][1], bL[2*pp+1][0], bL[2*pp+1][1], Blo + swo);
            }
            #pragma unroll
            for (int mt = 0; mt < 2; mt++)
                #pragma unroll
                for (int nn = 0; nn < 4; nn++) {
                    mma16816(acc[mt][nn], aH[mt], bH[nn]);   // hi*hi
                    mma16816(acc[mt][nn], aL[mt], bH[nn]);   // lo*hi
                    mma16816(acc[mt][nn], aH[mt], bL[nn]);   // hi*lo
                }
        }
    }

    // epilogue: lane holds, per (mt, ri), 2 f's (up) with all 4 gates each
    {
        const int c_l = lane & 3;
        const int r_l = lane >> 2;
        #pragma unroll
        for (int mt = 0; mt < 2; mt++)
        #pragma unroll
        for (int ri = 0; ri < 2; ri++) {
            const int m = m0 + rbaseA + mt*16 + ri*8 + r_l;
            #pragma unroll
            for (int up = 0; up < 2; up++) {
                const int u_abs = w_n*2 + up;
                const int f = f0 + 4*u_abs + c_l;
                const int jb = 16*u_abs + 2*c_l;
                float gi = acc[mt][2*up  ][ri*2    ] + bias_s[jb];
                float gf = acc[mt][2*up  ][ri*2 + 1] + bias_s[jb + 1];
                float gg = acc[mt][2*up+1][ri*2    ] + bias_s[jb + 8];
                float go = acc[mt][2*up+1][ri*2 + 1] + bias_s[jb + 9];
                float si = 1.0f / (1.0f + __expf(-gi));
                float sf = 1.0f / (1.0f + __expf(-gf));
                float tg = tanhf(gg);
                float so = 1.0f / (1.0f + __expf(-go));
                size_t idx = (size_t)m*FF + f;
                float cn = sf * C[idx] + si * tg;
                float hn = so * tanhf(cn);
                C[idx] = cn;
                __nv_bfloat16 hib = __float2bfloat16(hn);
                HWhi[idx] = hib;
                HWlo[idx] = __float2bfloat16(hn - __bfloat162float(hib));
                if (out_t >= 0) out[idx*FUT + out_t] = hn;
            }
        }
    }
}

// ---------------- host --------------------------------------------------------
extern "C" void kernel_launch(void* const* d_in, const int* in_sizes, int n_in,
                              void* d_out, int out_size)
{
    (void)in_sizes; (void)n_in; (void)out_size;
    const float* seq = (const float*)d_in[0];
    const float* Wih = (const float*)d_in[1];
    const float* Whh = (const float*)d_in[2];
    const float* bih = (const float*)d_in[3];
    const float* bhh = (const float*)d_in[4];
    float* out = (float*)d_out;

    cudaFuncSetAttribute(lstm_cell, cudaFuncAttributeMaxDynamicSharedMemorySize,
                         SMEM_REQ);

    __nv_bfloat16 *pW, *pxhi, *pxlo, *phhi, *phlo, *pcinhi, *pcinlo;
    float *pc;
    cudaGetSymbolAddress((void**)&pW,     g_W);
    cudaGetSymbolAddress((void**)&pxhi,   g_xhi);
    cudaGetSymbolAddress((void**)&pxlo,   g_xlo);
    cudaGetSymbolAddress((void**)&phhi,   g_hhi);
    cudaGetSymbolAddress((void**)&phlo,   g_hlo);
    cudaGetSymbolAddress((void**)&pc,     g_c);
    cudaGetSymbolAddress((void**)&pcinhi, g_cinhi);
    cudaGetSymbolAddress((void**)&pcinlo, g_cinlo);

    const int PLANE = BB*FF;
    {
        long nw = 3L*4096*2048;
        prep_weights<<<(unsigned)((nw + 255)/256), 256>>>(Wih, Whh);
        prep_x<<<(PLANE + 255)/256, 256>>>(seq);
        int nz = 2*NL*PLANE;
        zero_state<<<(nz + 255)/256, 256>>>();
    }

    dim3 grid(FF/32, BB/TM);   // (32, 4) = 128 CTAs
    for (int s = 0; s < HIST + FUT; s++) {
        const int rh = s & 1, wh = rh ^ 1;
        const bool fut = (s >= HIST);
        const int j = s - HIST;
        if (fut && j == 0) prep_cin<<<(PLANE + 255)/256, 256>>>();
        for (int l = 0; l < NL; l++) {
            const __nv_bfloat16 *Xhi, *Xlo;
            if (l > 0)        { Xhi = phhi + (size_t)(wh*NL + (l-1))*PLANE;
                                Xlo = phlo + (size_t)(wh*NL + (l-1))*PLANE; }
            else if (!fut)    { Xhi = pxhi + (size_t)s*PLANE;
                                Xlo = pxlo + (size_t)s*PLANE; }
            else if (j == 0)  { Xhi = pcinhi; Xlo = pcinlo; }
            else              { Xhi = phhi + (size_t)(rh*NL + (NL-1))*PLANE;
                                Xlo = phlo + (size_t)(rh*NL + (NL-1))*PLANE; }
            const __nv_bfloat16* Hhi = phhi + (size_t)(rh*NL + l)*PLANE;
            const __nv_bfloat16* Hlo = phlo + (size_t)(rh*NL + l)*PLANE;
            __nv_bfloat16* HWhi = phhi + (size_t)(wh*NL + l)*PLANE;
            __nv_bfloat16* HWlo = phlo + (size_t)(wh*NL + l)*PLANE;
            float* C = pc + (size_t)l*PLANE;
            const __nv_bfloat16* Wlay = pW + (size_t)l*32*32*2*8192;
            int out_t = (fut && l == NL-1) ? j : -1;
            lstm_cell<<<grid, 512, SMEM_REQ>>>(Xhi, Xlo, Hhi, Hlo, HWhi, HWlo,
                                               C, Wlay,
                                               bih + (size_t)l*4*FF,
                                               bhh + (size_t)l*4*FF,
                                               out, out_t);
        }
    }
}

// round 8
// speedup vs baseline: 2.0847x; 2.0847x over previous
#include <cuda_runtime.h>
#include <cuda_bf16.h>
#include <math.h>
#include <stdint.h>

#define BB   512
#define FF   1024
#define HIST 20
#define FUT  30
#define NL   3

#define TM   128
#define KC   64
#define NCH  32
#define NSTG 3

#define SMEM_STAGE 65536
#define OFF_MBAR   (NSTG*SMEM_STAGE)
#define OFF_TPTR   (OFF_MBAR + 32)
#define OFF_BIAS   (OFF_MBAR + 64)
#define SMEM_REQ   (OFF_BIAS + 512 + 1024)

#if defined(__CUDA_ARCH_FEAT_SM103_ALL) || defined(__CUDA_ARCH_FEAT_SM100_ALL)
#define USE_TC 1
#else
#define USE_TC 0
#endif

// idesc kind::f16: dtype=F32, atype=BF16, btype=BF16, N=128, M=128
#define IDESC 0x08200490u

// ---------------- device globals ---------------------------------------------
// Weights hi/lo pre-swizzled into SMEM tile layout, 16KB blocks:
// block ((l*32 + nt)*32 + kc)*2 + plane.  Column j = 16u + 8*(g>=2) + 2c + (g&1)
// where f_local = 4u + c  (all 4 gates of an f share one mma/TMEM lane group).
__device__ __nv_bfloat16 g_W[(size_t)3*32*32*2*8192];
__device__ __nv_bfloat16 g_xhi[HIST][BB*FF];
__device__ __nv_bfloat16 g_xlo[HIST][BB*FF];
__device__ __nv_bfloat16 g_hhi[2][NL][BB*FF];
__device__ __nv_bfloat16 g_hlo[2][NL][BB*FF];
__device__ float         g_c[NL][BB*FF];
__device__ __nv_bfloat16 g_cinhi[BB*FF];
__device__ __nv_bfloat16 g_cinlo[BB*FF];

// ---------------- common helpers ---------------------------------------------
#define CP16(dst, src) \
    asm volatile("cp.async.ca.shared.global [%0], [%1], 16;" \
        :: "r"((uint32_t)(dst)), "l"(src) : "memory")

__device__ __forceinline__ void ldsm4(uint32_t& r0, uint32_t& r1,
                                      uint32_t& r2, uint32_t& r3, uint32_t addr) {
    asm volatile("ldmatrix.sync.aligned.m8n8.x4.shared.b16 {%0,%1,%2,%3}, [%4];"
                 : "=r"(r0), "=r"(r1), "=r"(r2), "=r"(r3) : "r"(addr));
}
__device__ __forceinline__ void mma16816(float* c, const uint32_t* a,
                                         const uint32_t* b) {
    asm volatile("mma.sync.aligned.m16n8k16.row.col.f32.bf16.bf16.f32 "
        "{%0,%1,%2,%3}, {%4,%5,%6,%7}, {%8,%9}, {%0,%1,%2,%3};"
        : "+f"(c[0]), "+f"(c[1]), "+f"(c[2]), "+f"(c[3])
        : "r"(a[0]), "r"(a[1]), "r"(a[2]), "r"(a[3]), "r"(b[0]), "r"(b[1]));
}

#if USE_TC
__device__ __forceinline__ uint32_t elect_one_pred() {
    uint32_t pred;
    asm volatile("{\n\t.reg .pred p;\n\telect.sync _|p, 0xFFFFFFFF;\n\t"
                 "selp.b32 %0, 1, 0, p;\n\t}" : "=r"(pred));
    return pred;
}
#define TCGEN05_ALLOC(smem_addr, nCols) \
    asm volatile("tcgen05.alloc.cta_group::1.sync.aligned.shared::cta.b32 [%0], %1;" \
        :: "r"((uint32_t)(smem_addr)), "r"((uint32_t)(nCols)) : "memory")
#define TCGEN05_DEALLOC(tmem_addr, nCols) \
    asm volatile("tcgen05.dealloc.cta_group::1.sync.aligned.b32 %0, %1;" \
        :: "r"(tmem_addr), "r"((uint32_t)(nCols)))
#define TCGEN05_COMMIT(mbar) \
    asm volatile("tcgen05.commit.cta_group::1.mbarrier::arrive::one.shared::cluster.b64 [%0];" \
        :: "r"((uint32_t)(mbar)) : "memory")
#define TCGEN05_FENCE_AFTER() \
    asm volatile("tcgen05.fence::after_thread_sync;" ::: "memory")
#define TCGEN05_WAIT_LD() \
    asm volatile("tcgen05.wait::ld.sync.aligned;" ::: "memory")
#define MBARRIER_INIT(mbar, cnt) \
    asm volatile("mbarrier.init.shared.b64 [%0], %1;" \
        :: "r"((uint32_t)(mbar)), "r"((uint32_t)(cnt)) : "memory")
#define MBARRIER_INVAL(mbar) \
    asm volatile("mbarrier.inval.shared.b64 [%0];" :: "r"((uint32_t)(mbar)) : "memory")
#define MBARRIER_WAIT_PARITY(mbar, parity) do { \
    uint32_t _m = (uint32_t)(mbar); uint32_t _p = (uint32_t)(parity); uint32_t _done; \
    asm volatile("{\n\t.reg .pred p;\n\t" \
        "mbarrier.try_wait.parity.acquire.cta.shared::cta.b64 p, [%1], %2;\n\t" \
        "selp.b32 %0, 1, 0, p;\n\t}" : "=r"(_done) : "r"(_m), "r"(_p) : "memory"); \
    if (!_done) { \
        asm volatile("{\n\t.reg .pred P1;\n\t" \
            "WL_%=:\n\t" \
            "mbarrier.try_wait.parity.acquire.cta.shared::cta.b64 P1, [%0], %1, 0x989680;\n\t" \
            "@P1 bra.uni WD_%=;\n\tbra.uni WL_%=;\n\tWD_%=:\n\t}" \
            :: "r"(_m), "r"(_p) : "memory"); \
    } } while (0)
#define TCGEN05_LD_32X32B_X32(r, tmem_addr) \
    asm volatile("tcgen05.ld.sync.aligned.32x32b.x32.b32 " \
        "{%0, %1, %2, %3, %4, %5, %6, %7, %8, %9, %10, %11, %12, %13, %14, %15, " \
        " %16, %17, %18, %19, %20, %21, %22, %23, %24, %25, %26, %27, %28, %29, %30, %31}, [%32];" \
        : "=r"((r)[0]),  "=r"((r)[1]),  "=r"((r)[2]),  "=r"((r)[3]), \
          "=r"((r)[4]),  "=r"((r)[5]),  "=r"((r)[6]),  "=r"((r)[7]), \
          "=r"((r)[8]),  "=r"((r)[9]),  "=r"((r)[10]), "=r"((r)[11]), \
          "=r"((r)[12]), "=r"((r)[13]), "=r"((r)[14]), "=r"((r)[15]), \
          "=r"((r)[16]), "=r"((r)[17]), "=r"((r)[18]), "=r"((r)[19]), \
          "=r"((r)[20]), "=r"((r)[21]), "=r"((r)[22]), "=r"((r)[23]), \
          "=r"((r)[24]), "=r"((r)[25]), "=r"((r)[26]), "=r"((r)[27]), \
          "=r"((r)[28]), "=r"((r)[29]), "=r"((r)[30]), "=r"((r)[31]) \
        : "r"(tmem_addr))

static constexpr uint64_t SMEM_DESC_BASE_SW128 =
    (uint64_t(2) << 61) | (uint64_t(1) << 46) | (uint64_t(64) << 32) | (uint64_t(1) << 16);
#define MAKE_SMEM_DESC(base_addr) \
    (SMEM_DESC_BASE_SW128 | ((uint64_t)((base_addr) >> 4) & 0x3FFF))

__device__ __forceinline__ void mma_f16_ss(uint32_t d, uint64_t a, uint64_t b,
                                           uint32_t en) {
    asm volatile("{\n\t.reg .pred p;\n\tsetp.ne.u32 p, %5, 0;\n\t"
        "tcgen05.mma.cta_group::1.kind::f16 [%0], %1, %2, %3, {%4,%4,%4,%4}, p;\n\t}"
        :: "r"(d), "l"(a), "l"(b), "r"(IDESC), "r"(0u), "r"(en) : "memory");
}
#endif  // USE_TC

// ---------------- prep kernels -----------------------------------------------
__global__ void prep_weights(const float* __restrict__ Wih,
                             const float* __restrict__ Whh) {
    long i = (long)blockIdx.x * blockDim.x + threadIdx.x;
    if (i >= 3L*4096*2048) return;
    int  k     = (int)(i & 2047);
    long r     = i >> 11;
    int  row_w = (int)(r & 4095);
    int  l     = (int)(r >> 12);
    float w = (k < 1024)
        ? Wih[(long)l*4096*1024 + (long)row_w*1024 + k]
        : Whh[(long)l*4096*1024 + (long)row_w*1024 + (k-1024)];
    __nv_bfloat16 hi = __float2bfloat16(w);
    __nv_bfloat16 lo = __float2bfloat16(w - __bfloat162float(hi));
    int g = row_w >> 10, f = row_w & 1023;
    int nt = f >> 5, fl = f & 31;
    int j = ((fl >> 2) << 4) | ((g >> 1) << 3) | ((fl & 3) << 1) | (g & 1);
    int kc = k >> 6, kl = k & 63;
    int off = j*128 + kl*2;
    off ^= (off >> 3) & 0x70;
    long blk = (((long)l*32 + nt)*32 + kc)*2;
    g_W[(blk + 0)*8192 + (off >> 1)] = hi;
    g_W[(blk + 1)*8192 + (off >> 1)] = lo;
}

__global__ void prep_x(const float* __restrict__ seq) {
    int i = blockIdx.x * blockDim.x + threadIdx.x;
    if (i >= BB*FF) return;
    const float* s = seq + (size_t)i * HIST;
    #pragma unroll
    for (int t = 0; t < HIST; t++) {
        float v = s[t];
        __nv_bfloat16 hi = __float2bfloat16(v);
        g_xhi[t][i] = hi;
        g_xlo[t][i] = __float2bfloat16(v - __bfloat162float(hi));
    }
}

__global__ void zero_state() {
    int i = blockIdx.x * blockDim.x + threadIdx.x;
    if (i < 2*NL*BB*FF) {
        ((unsigned short*)g_hhi)[i] = 0;
        ((unsigned short*)g_hlo)[i] = 0;
    }
    if (i < NL*BB*FF) ((float*)g_c)[i] = 0.0f;
}

__global__ void prep_cin() {
    int i = blockIdx.x * blockDim.x + threadIdx.x;
    if (i >= BB*FF) return;
    float v = g_c[NL-1][i];
    __nv_bfloat16 hi = __float2bfloat16(v);
    g_cinhi[i] = hi;
    g_cinlo[i] = __float2bfloat16(v - __bfloat162float(hi));
}

// ---------------- chunk loader (256 threads) ----------------------------------
__device__ __forceinline__ void load_chunk(uint32_t stage, int kc,
    const __nv_bfloat16* Xhi, const __nv_bfloat16* Xlo,
    const __nv_bfloat16* Hhi, const __nv_bfloat16* Hlo,
    const __nv_bfloat16* Wnt, int m0, int t)
{
    const __nv_bfloat16 *phi, *plo; int kb;
    if (kc < 16) { phi = Xhi; plo = Xlo; kb = kc * KC; }
    else         { phi = Hhi; plo = Hlo; kb = (kc-16) * KC; }
    const uint32_t Ahi = stage, Alo = stage + 16384;
    const uint32_t Bhi = stage + 32768, Blo = stage + 49152;
    const int ku = t & 7, rb = t >> 3;          // rb 0..31
    #pragma unroll
    for (int p = 0; p < 4; p++) {
        int row = p*32 + rb;
        int ob  = row*128 + ku*16;
        int swo = ob ^ ((ob >> 3) & 0x70);
        size_t sidx = (size_t)(m0 + row)*FF + kb + ku*8;
        CP16(Ahi + swo, phi + sidx);
        CP16(Alo + swo, plo + sidx);
    }
    const char* wb = (const char*)(Wnt + (size_t)kc*2*8192);
    #pragma unroll
    for (int o = 0; o < 4; o++) {
        int off = o*4096 + t*16;
        CP16(Bhi + off, wb + off);
        CP16(Blo + off, wb + 16384 + off);
    }
}

// ---------------- fused LSTM cell ---------------------------------------------
extern __shared__ char dsm[];

__global__ __launch_bounds__(256, 1)
void lstm_cell(const __nv_bfloat16* __restrict__ Xhi,
               const __nv_bfloat16* __restrict__ Xlo,
               const __nv_bfloat16* __restrict__ Hhi,
               const __nv_bfloat16* __restrict__ Hlo,
               __nv_bfloat16* __restrict__ HWhi,
               __nv_bfloat16* __restrict__ HWlo,
               float* __restrict__ C,
               const __nv_bfloat16* __restrict__ Wlay,
               const float* __restrict__ bih,
               const float* __restrict__ bhh,
               float* __restrict__ out, int out_t)
{
    char* base = (char*)(((uintptr_t)dsm + 1023) & ~(uintptr_t)1023);
    uint32_t sb;
    asm("{ .reg .u64 tmp; cvta.to.shared.u64 tmp, %1; cvt.u32.u64 %0, tmp; }"
        : "=r"(sb) : "l"(base));

    const int t    = threadIdx.x;
    const int w    = t >> 5;
    const int lane = t & 31;
    const int nt   = blockIdx.x;
    const int m0   = blockIdx.y * TM;
    const int f0   = nt * 32;
    float* bias_s  = (float*)(base + OFF_BIAS);

    if (t < 128) {   // bias_s[j]: decode j -> (f, g)
        int u = t >> 4, g = ((t >> 3) & 1)*2 + (t & 1), c = (t >> 1) & 3;
        int f = f0 + 4*u + c;
        bias_s[t] = bih[g*FF + f] + bhh[g*FF + f];
    }
#if USE_TC
    if (w == 0) TCGEN05_ALLOC(sb + OFF_TPTR, 128);
    if (t == 0) {
        #pragma unroll
        for (int s = 0; s < NSTG; s++) MBARRIER_INIT(sb + OFF_MBAR + s*8, 1);
    }
#endif
    __syncthreads();

    const __nv_bfloat16* Wnt = Wlay + (size_t)nt * (32*2*8192);

#if USE_TC
    // ============ tcgen05 path (sm_103a cubin) — pipelined =================
    uint32_t tmem = *(uint32_t*)(base + OFF_TPTR);
    int ph[NSTG] = {0, 0, 0};

    // prologue: distance-2 prefetch
    load_chunk(sb + 0*SMEM_STAGE, 0, Xhi, Xlo, Hhi, Hlo, Wnt, m0, t);
    asm volatile("cp.async.commit_group;" ::: "memory");
    load_chunk(sb + 1*SMEM_STAGE, 1, Xhi, Xlo, Hhi, Hlo, Wnt, m0, t);
    asm volatile("cp.async.commit_group;" ::: "memory");

    for (int kc = 0; kc < NCH; kc++) {
        const int s = kc % NSTG;

        // loads of chunk kc complete (kc+1 may stay in flight)
        if (kc + 1 < NCH) asm volatile("cp.async.wait_group 1;" ::: "memory");
        else              asm volatile("cp.async.wait_group 0;" ::: "memory");
        __syncthreads();

        // reuse stage (kc+2)%NSTG == (kc-1)%NSTG: wait MMA of chunk kc-1
        if (kc >= 1 && kc + 2 < NCH) {
            const int sw = (kc - 1) % NSTG;
            MBARRIER_WAIT_PARITY(sb + OFF_MBAR + sw*8, ph[sw]);
            ph[sw] ^= 1;
            load_chunk(sb + sw*SMEM_STAGE, kc + 2, Xhi, Xlo, Hhi, Hlo, Wnt, m0, t);
            asm volatile("cp.async.commit_group;" ::: "memory");
        } else if (kc == 0) {
            load_chunk(sb + 2*SMEM_STAGE, 2, Xhi, Xlo, Hhi, Hlo, Wnt, m0, t);
            asm volatile("cp.async.commit_group;" ::: "memory");
        }

        if (w == 0) {
            asm volatile("fence.proxy.async.shared::cta;" ::: "memory");
            if (elect_one_pred()) {
                const uint32_t stage = sb + s*SMEM_STAGE;
                uint64_t dah = MAKE_SMEM_DESC(stage);
                uint64_t dal = MAKE_SMEM_DESC(stage + 16384);
                uint64_t dbh = MAKE_SMEM_DESC(stage + 32768);
                uint64_t dbl = MAKE_SMEM_DESC(stage + 49152);
                #pragma unroll
                for (int ks = 0; ks < 4; ks++)      // hi*hi
                    mma_f16_ss(tmem, dah + ks*2, dbh + ks*2, !(kc == 0 && ks == 0));
                #pragma unroll
                for (int ks = 0; ks < 4; ks++)      // hi*lo
                    mma_f16_ss(tmem, dah + ks*2, dbl + ks*2, 1u);
                #pragma unroll
                for (int ks = 0; ks < 4; ks++)      // lo*hi
                    mma_f16_ss(tmem, dal + ks*2, dbh + ks*2, 1u);
                TCGEN05_COMMIT(sb + OFF_MBAR + s*8);
            }
        }
    }

    // drain outstanding MMA commits (chunks NCH-3..NCH-1, distinct mbar slots)
    #pragma unroll
    for (int s = 0; s < NSTG; s++) MBARRIER_WAIT_PARITY(sb + OFF_MBAR + s*8, ph[s]);
    TCGEN05_FENCE_AFTER();

    // epilogue: warp w -> rows (w&3)*32 + lane, parts (w>>2)*2 + {0,1}
    {
        const int m = m0 + (w & 3)*32 + lane;
        float* crow = C + (size_t)m*FF + f0;
        #pragma unroll
        for (int pp = 0; pp < 2; pp++) {
            const int part = (w >> 2)*2 + pp;
            uint32_t d[32];
            TCGEN05_LD_32X32B_X32(d, tmem + part*32);
            TCGEN05_WAIT_LD();
            float4 c0 = *(const float4*)(crow + part*8);
            float4 c1 = *(const float4*)(crow + part*8 + 4);
            float cin[8] = {c0.x, c0.y, c0.z, c0.w, c1.x, c1.y, c1.z, c1.w};
            float cnew[8], hnew[8];
            __nv_bfloat16 hh[8], hl[8];
            #pragma unroll
            for (int fr = 0; fr < 8; fr++) {
                int qb = ((fr >> 2) << 4) + ((fr & 3) << 1);
                float gi = __uint_as_float(d[qb])   + bias_s[part*32 + qb];
                float gf = __uint_as_float(d[qb+1]) + bias_s[part*32 + qb+1];
                float gg = __uint_as_float(d[qb+8]) + bias_s[part*32 + qb+8];
                float go = __uint_as_float(d[qb+9]) + bias_s[part*32 + qb+9];
                float si = 1.0f / (1.0f + __expf(-gi));
                float sf = 1.0f / (1.0f + __expf(-gf));
                float tg = tanhf(gg);
                float so = 1.0f / (1.0f + __expf(-go));
                float cn = sf * cin[fr] + si * tg;
                float hn = so * tanhf(cn);
                cnew[fr] = cn; hnew[fr] = hn;
                __nv_bfloat16 hib = __float2bfloat16(hn);
                hh[fr] = hib;
                hl[fr] = __float2bfloat16(hn - __bfloat162float(hib));
            }
            *(float4*)(crow + part*8)     = make_float4(cnew[0], cnew[1], cnew[2], cnew[3]);
            *(float4*)(crow + part*8 + 4) = make_float4(cnew[4], cnew[5], cnew[6], cnew[7]);
            *(uint4*)(HWhi + (size_t)m*FF + f0 + part*8) = *(const uint4*)hh;
            *(uint4*)(HWlo + (size_t)m*FF + f0 + part*8) = *(const uint4*)hl;
            if (out_t >= 0) {
                #pragma unroll
                for (int fr = 0; fr < 8; fr++)
                    out[((size_t)m*FF + f0 + part*8 + fr)*FUT + out_t] = hnew[fr];
            }
        }
    }
    __syncthreads();
    if (t == 0) {
        #pragma unroll
        for (int s = 0; s < NSTG; s++) MBARRIER_INVAL(sb + OFF_MBAR + s*8);
    }
    __syncthreads();
    if (w == 0) TCGEN05_DEALLOC(tmem, 128);

#else
    // ============ mma.sync HMMA fallback (compute_103 pass) ================
    float acc[2][8][4];
    #pragma unroll
    for (int a = 0; a < 2; a++)
        #pragma unroll
        for (int b = 0; b < 8; b++)
            #pragma unroll
            for (int c = 0; c < 4; c++) acc[a][b][c] = 0.0f;

    const int rbaseA = (w & 3) * 32;
    const int ntb    = (w >> 2) * 8;
    const int a_ro   = (lane & 7) + ((lane >> 3) & 1)*8;
    const int a_bh   = (lane >> 4) * 16;
    const int b_jo   = lane & 7;
    const int b_bh   = ((lane >> 3) & 1) * 16;
    const int b_ts   = lane >> 4;

    load_chunk(sb, 0, Xhi, Xlo, Hhi, Hlo, Wnt, m0, t);
    asm volatile("cp.async.commit_group;" ::: "memory");

    for (int kc = 0; kc < NCH; kc++) {
        if (kc + 1 < NCH) {
            load_chunk(sb + ((kc+1) % NSTG)*SMEM_STAGE, kc + 1,
                       Xhi, Xlo, Hhi, Hlo, Wnt, m0, t);
            asm volatile("cp.async.commit_group;" ::: "memory");
            asm volatile("cp.async.wait_group 1;" ::: "memory");
        } else {
            asm volatile("cp.async.wait_group 0;" ::: "memory");
        }
        __syncthreads();

        const uint32_t stage = sb + (kc % NSTG)*SMEM_STAGE;
        const uint32_t Ahi = stage, Alo = stage + 16384;
        const uint32_t Bhi = stage + 32768, Blo = stage + 49152;

        #pragma unroll
        for (int s16 = 0; s16 < 4; s16++) {
            uint32_t aH[2][4], aL[2][4], bH[8][2], bL[8][2];
            const int abyte = s16*32 + a_bh;
            #pragma unroll
            for (int mt = 0; mt < 2; mt++) {
                int row = rbaseA + mt*16 + a_ro;
                int ob  = row*128 + abyte;
                int swo = ob ^ ((ob >> 3) & 0x70);
                ldsm4(aH[mt][0], aH[mt][1], aH[mt][2], aH[mt][3], Ahi + swo);
                ldsm4(aL[mt][0], aL[mt][1], aL[mt][2], aL[mt][3], Alo + swo);
            }
            const int bbyte = s16*32 + b_bh;
            #pragma unroll
            for (int pp = 0; pp < 4; pp++) {
                int j  = (ntb + 2*pp + b_ts)*8 + b_jo;
                int ob = j*128 + bbyte;
                int swo = ob ^ ((ob >> 3) & 0x70);
                ldsm4(bH[2*pp][0], bH[2*pp][1], bH[2*pp+1][0], bH[2*pp+1][1], Bhi + swo);
                ldsm4(bL[2*pp][0], bL[2*pp][1], bL[2*pp+1][0], bL[2*pp+1][1], Blo + swo);
            }
            #pragma unroll
            for (int mt = 0; mt < 2; mt++)
                #pragma unroll
                for (int nn = 0; nn < 8; nn++) {
                    mma16816(acc[mt][nn], aH[mt], bH[nn]);
                    mma16816(acc[mt][nn], aL[mt], bH[nn]);
                    mma16816(acc[mt][nn], aH[mt], bL[nn]);
                }
        }
        __syncthreads();
    }

    {
        const int c_l = lane & 3;
        const int r_l = lane >> 2;
        #pragma unroll
        for (int mt = 0; mt < 2; mt++)
        #pragma unroll
        for (int ri = 0; ri < 2; ri++) {
            const int m = m0 + rbaseA + mt*16 + ri*8 + r_l;
            #pragma unroll
            for (int up = 0; up < 4; up++) {
                const int u_abs = (w >> 2)*4 + up;
                const int f = f0 + 4*u_abs + c_l;
                const int jb = 16*u_abs + 2*c_l;
                float gi = acc[mt][2*up  ][ri*2    ] + bias_s[jb];
                float gf = acc[mt][2*up  ][ri*2 + 1] + bias_s[jb + 1];
                float gg = acc[mt][2*up+1][ri*2    ] + bias_s[jb + 8];
                float go = acc[mt][2*up+1][ri*2 + 1] + bias_s[jb + 9];
                float si = 1.0f / (1.0f + __expf(-gi));
                float sf = 1.0f / (1.0f + __expf(-gf));
                float tg = tanhf(gg);
                float so = 1.0f / (1.0f + __expf(-go));
                size_t idx = (size_t)m*FF + f;
                float cn = sf * C[idx] + si * tg;
                float hn = so * tanhf(cn);
                C[idx] = cn;
                __nv_bfloat16 hib = __float2bfloat16(hn);
                HWhi[idx] = hib;
                HWlo[idx] = __float2bfloat16(hn - __bfloat162float(hib));
                if (out_t >= 0) out[idx*FUT + out_t] = hn;
            }
        }
    }
#endif
}

// ---------------- host --------------------------------------------------------
extern "C" void kernel_launch(void* const* d_in, const int* in_sizes, int n_in,
                              void* d_out, int out_size)
{
    (void)in_sizes; (void)n_in; (void)out_size;
    const float* seq = (const float*)d_in[0];
    const float* Wih = (const float*)d_in[1];
    const float* Whh = (const float*)d_in[2];
    const float* bih = (const float*)d_in[3];
    const float* bhh = (const float*)d_in[4];
    float* out = (float*)d_out;

    cudaFuncSetAttribute(lstm_cell, cudaFuncAttributeMaxDynamicSharedMemorySize,
                         SMEM_REQ);

    __nv_bfloat16 *pW, *pxhi, *pxlo, *phhi, *phlo, *pcinhi, *pcinlo;
    float *pc;
    cudaGetSymbolAddress((void**)&pW,     g_W);
    cudaGetSymbolAddress((void**)&pxhi,   g_xhi);
    cudaGetSymbolAddress((void**)&pxlo,   g_xlo);
    cudaGetSymbolAddress((void**)&phhi,   g_hhi);
    cudaGetSymbolAddress((void**)&phlo,   g_hlo);
    cudaGetSymbolAddress((void**)&pc,     g_c);
    cudaGetSymbolAddress((void**)&pcinhi, g_cinhi);
    cudaGetSymbolAddress((void**)&pcinlo, g_cinlo);

    const int PLANE = BB*FF;
    {
        long nw = 3L*4096*2048;
        prep_weights<<<(unsigned)((nw + 255)/256), 256>>>(Wih, Whh);
        prep_x<<<(PLANE + 255)/256, 256>>>(seq);
        int nz = 2*NL*PLANE;
        zero_state<<<(nz + 255)/256, 256>>>();
    }

    dim3 grid(FF/32, BB/TM);   // (32, 4) = 128 CTAs
    for (int s = 0; s < HIST + FUT; s++) {
        const int rh = s & 1, wh = rh ^ 1;
        const bool fut = (s >= HIST);
        const int j = s - HIST;
        if (fut && j == 0) prep_cin<<<(PLANE + 255)/256, 256>>>();
        for (int l = 0; l < NL; l++) {
            const __nv_bfloat16 *Xhi, *Xlo;
            if (l > 0)        { Xhi = phhi + (size_t)(wh*NL + (l-1))*PLANE;
                                Xlo = phlo + (size_t)(wh*NL + (l-1))*PLANE; }
            else if (!fut)    { Xhi = pxhi + (size_t)s*PLANE;
                                Xlo = pxlo + (size_t)s*PLANE; }
            else if (j == 0)  { Xhi = pcinhi; Xlo = pcinlo; }
            else              { Xhi = phhi + (size_t)(rh*NL + (NL-1))*PLANE;
                                Xlo = phlo + (size_t)(rh*NL + (NL-1))*PLANE; }
            const __nv_bfloat16* Hhi = phhi + (size_t)(rh*NL + l)*PLANE;
            const __nv_bfloat16* Hlo = phlo + (size_t)(rh*NL + l)*PLANE;
            __nv_bfloat16* HWhi = phhi + (size_t)(wh*NL + l)*PLANE;
            __nv_bfloat16* HWlo = phlo + (size_t)(wh*NL + l)*PLANE;
            float* C = pc + (size_t)l*PLANE;
            const __nv_bfloat16* Wlay = pW + (size_t)l*32*32*2*8192;
            int out_t = (fut && l == NL-1) ? j : -1;
            lstm_cell<<<grid, 256, SMEM_REQ>>>(Xhi, Xlo, Hhi, Hlo, HWhi, HWlo,
                                               C, Wlay,
                                               bih + (size_t)l*4*FF,
                                               bhh + (size_t)l*4*FF,
                                               out, out_t);
        }
    }
}

// round 9
// speedup vs baseline: 2.4652x; 1.1825x over previous
#include <cuda_runtime.h>
#include <cuda_bf16.h>
#include <math.h>
#include <stdint.h>

#define BB   512
#define FF   1024
#define HIST 20
#define FUT  30
#define NL   3

#define TM   128
#define KC   64
#define NCH  32
#define NSTG 3

#define SMEM_STAGE 65536
#define OFF_MBAR   (NSTG*SMEM_STAGE)
#define OFF_TPTR   (OFF_MBAR + 32)
#define OFF_BIAS   (OFF_MBAR + 64)
#define SMEM_REQ   (OFF_BIAS + 512 + 1024)

#if defined(__CUDA_ARCH_FEAT_SM103_ALL) || defined(__CUDA_ARCH_FEAT_SM100_ALL)
#define USE_TC 1
#else
#define USE_TC 0
#endif

// idesc kind::f16: dtype=F32, atype=BF16, btype=BF16, N=128, M=128
#define IDESC 0x08200490u

// ---------------- device globals ---------------------------------------------
// Weights hi/lo pre-swizzled into SMEM tile layout, 16KB blocks:
// block ((l*32 + nt)*32 + kc)*2 + plane.  Column j = 16u + 8*(g>=2) + 2c + (g&1)
// where f_local = 4u + c  (all 4 gates of an f share one mma/TMEM lane group).
__device__ __nv_bfloat16 g_W[(size_t)3*32*32*2*8192];
__device__ __nv_bfloat16 g_xhi[HIST][BB*FF];
__device__ __nv_bfloat16 g_xlo[HIST][BB*FF];
__device__ __nv_bfloat16 g_hhi[2][NL][BB*FF];
__device__ __nv_bfloat16 g_hlo[2][NL][BB*FF];
__device__ float         g_c[NL][BB*FF];
__device__ __nv_bfloat16 g_cinhi[BB*FF];
__device__ __nv_bfloat16 g_cinlo[BB*FF];

// ---------------- common helpers ---------------------------------------------
#define CP16(dst, src) \
    asm volatile("cp.async.cg.shared.global [%0], [%1], 16;" \
        :: "r"((uint32_t)(dst)), "l"(src) : "memory")

__device__ __forceinline__ void ldsm4(uint32_t& r0, uint32_t& r1,
                                      uint32_t& r2, uint32_t& r3, uint32_t addr) {
    asm volatile("ldmatrix.sync.aligned.m8n8.x4.shared.b16 {%0,%1,%2,%3}, [%4];"
                 : "=r"(r0), "=r"(r1), "=r"(r2), "=r"(r3) : "r"(addr));
}
__device__ __forceinline__ void mma16816(float* c, const uint32_t* a,
                                         const uint32_t* b) {
    asm volatile("mma.sync.aligned.m16n8k16.row.col.f32.bf16.bf16.f32 "
        "{%0,%1,%2,%3}, {%4,%5,%6,%7}, {%8,%9}, {%0,%1,%2,%3};"
        : "+f"(c[0]), "+f"(c[1]), "+f"(c[2]), "+f"(c[3])
        : "r"(a[0]), "r"(a[1]), "r"(a[2]), "r"(a[3]), "r"(b[0]), "r"(b[1]));
}

#if USE_TC
__device__ __forceinline__ uint32_t elect_one_pred() {
    uint32_t pred;
    asm volatile("{\n\t.reg .pred p;\n\telect.sync _|p, 0xFFFFFFFF;\n\t"
                 "selp.b32 %0, 1, 0, p;\n\t}" : "=r"(pred));
    return pred;
}
#define TCGEN05_ALLOC(smem_addr, nCols) \
    asm volatile("tcgen05.alloc.cta_group::1.sync.aligned.shared::cta.b32 [%0], %1;" \
        :: "r"((uint32_t)(smem_addr)), "r"((uint32_t)(nCols)) : "memory")
#define TCGEN05_DEALLOC(tmem_addr, nCols) \
    asm volatile("tcgen05.dealloc.cta_group::1.sync.aligned.b32 %0, %1;" \
        :: "r"(tmem_addr), "r"((uint32_t)(nCols)))
#define TCGEN05_COMMIT(mbar) \
    asm volatile("tcgen05.commit.cta_group::1.mbarrier::arrive::one.shared::cluster.b64 [%0];" \
        :: "r"((uint32_t)(mbar)) : "memory")
#define TCGEN05_FENCE_AFTER() \
    asm volatile("tcgen05.fence::after_thread_sync;" ::: "memory")
#define TCGEN05_WAIT_LD() \
    asm volatile("tcgen05.wait::ld.sync.aligned;" ::: "memory")
#define MBARRIER_INIT(mbar, cnt) \
    asm volatile("mbarrier.init.shared.b64 [%0], %1;" \
        :: "r"((uint32_t)(mbar)), "r"((uint32_t)(cnt)) : "memory")
#define MBARRIER_INVAL(mbar) \
    asm volatile("mbarrier.inval.shared.b64 [%0];" :: "r"((uint32_t)(mbar)) : "memory")
#define MBARRIER_WAIT_PARITY(mbar, parity) do { \
    uint32_t _m = (uint32_t)(mbar); uint32_t _p = (uint32_t)(parity); uint32_t _done; \
    asm volatile("{\n\t.reg .pred p;\n\t" \
        "mbarrier.try_wait.parity.acquire.cta.shared::cta.b64 p, [%1], %2;\n\t" \
        "selp.b32 %0, 1, 0, p;\n\t}" : "=r"(_done) : "r"(_m), "r"(_p) : "memory"); \
    if (!_done) { \
        asm volatile("{\n\t.reg .pred P1;\n\t" \
            "WL_%=:\n\t" \
            "mbarrier.try_wait.parity.acquire.cta.shared::cta.b64 P1, [%0], %1, 0x989680;\n\t" \
            "@P1 bra.uni WD_%=;\n\tbra.uni WL_%=;\n\tWD_%=:\n\t}" \
            :: "r"(_m), "r"(_p) : "memory"); \
    } } while (0)
#define TCGEN05_LD_32X32B_X32(r, tmem_addr) \
    asm volatile("tcgen05.ld.sync.aligned.32x32b.x32.b32 " \
        "{%0, %1, %2, %3, %4, %5, %6, %7, %8, %9, %10, %11, %12, %13, %14, %15, " \
        " %16, %17, %18, %19, %20, %21, %22, %23, %24, %25, %26, %27, %28, %29, %30, %31}, [%32];" \
        : "=r"((r)[0]),  "=r"((r)[1]),  "=r"((r)[2]),  "=r"((r)[3]), \
          "=r"((r)[4]),  "=r"((r)[5]),  "=r"((r)[6]),  "=r"((r)[7]), \
          "=r"((r)[8]),  "=r"((r)[9]),  "=r"((r)[10]), "=r"((r)[11]), \
          "=r"((r)[12]), "=r"((r)[13]), "=r"((r)[14]), "=r"((r)[15]), \
          "=r"((r)[16]), "=r"((r)[17]), "=r"((r)[18]), "=r"((r)[19]), \
          "=r"((r)[20]), "=r"((r)[21]), "=r"((r)[22]), "=r"((r)[23]), \
          "=r"((r)[24]), "=r"((r)[25]), "=r"((r)[26]), "=r"((r)[27]), \
          "=r"((r)[28]), "=r"((r)[29]), "=r"((r)[30]), "=r"((r)[31]) \
        : "r"(tmem_addr))

static constexpr uint64_t SMEM_DESC_BASE_SW128 =
    (uint64_t(2) << 61) | (uint64_t(1) << 46) | (uint64_t(64) << 32) | (uint64_t(1) << 16);
#define MAKE_SMEM_DESC(base_addr) \
    (SMEM_DESC_BASE_SW128 | ((uint64_t)((base_addr) >> 4) & 0x3FFF))

__device__ __forceinline__ void mma_f16_ss(uint32_t d, uint64_t a, uint64_t b,
                                           uint32_t en) {
    asm volatile("{\n\t.reg .pred p;\n\tsetp.ne.u32 p, %5, 0;\n\t"
        "tcgen05.mma.cta_group::1.kind::f16 [%0], %1, %2, %3, {%4,%4,%4,%4}, p;\n\t}"
        :: "r"(d), "l"(a), "l"(b), "r"(IDESC), "r"(0u), "r"(en) : "memory");
}
#endif  // USE_TC

// ---------------- prep kernels -----------------------------------------------
__global__ void prep_weights(const float* __restrict__ Wih,
                             const float* __restrict__ Whh) {
    long i = (long)blockIdx.x * blockDim.x + threadIdx.x;
    if (i >= 3L*4096*2048) return;
    int  k     = (int)(i & 2047);
    long r     = i >> 11;
    int  row_w = (int)(r & 4095);
    int  l     = (int)(r >> 12);
    float w = (k < 1024)
        ? Wih[(long)l*4096*1024 + (long)row_w*1024 + k]
        : Whh[(long)l*4096*1024 + (long)row_w*1024 + (k-1024)];
    __nv_bfloat16 hi = __float2bfloat16(w);
    __nv_bfloat16 lo = __float2bfloat16(w - __bfloat162float(hi));
    int g = row_w >> 10, f = row_w & 1023;
    int nt = f >> 5, fl = f & 31;
    int j = ((fl >> 2) << 4) | ((g >> 1) << 3) | ((fl & 3) << 1) | (g & 1);
    int kc = k >> 6, kl = k & 63;
    int off = j*128 + kl*2;
    off ^= (off >> 3) & 0x70;
    long blk = (((long)l*32 + nt)*32 + kc)*2;
    g_W[(blk + 0)*8192 + (off >> 1)] = hi;
    g_W[(blk + 1)*8192 + (off >> 1)] = lo;
}

__global__ void prep_x(const float* __restrict__ seq) {
    int i = blockIdx.x * blockDim.x + threadIdx.x;
    if (i >= BB*FF) return;
    const float* s = seq + (size_t)i * HIST;
    #pragma unroll
    for (int t = 0; t < HIST; t++) {
        float v = s[t];
        __nv_bfloat16 hi = __float2bfloat16(v);
        g_xhi[t][i] = hi;
        g_xlo[t][i] = __float2bfloat16(v - __bfloat162float(hi));
    }
}

__global__ void zero_state() {
    int i = blockIdx.x * blockDim.x + threadIdx.x;
    if (i < 2*NL*BB*FF) {
        ((unsigned short*)g_hhi)[i] = 0;
        ((unsigned short*)g_hlo)[i] = 0;
    }
    if (i < NL*BB*FF) ((float*)g_c)[i] = 0.0f;
}

__global__ void prep_cin() {
    int i = blockIdx.x * blockDim.x + threadIdx.x;
    if (i >= BB*FF) return;
    float v = g_c[NL-1][i];
    __nv_bfloat16 hi = __float2bfloat16(v);
    g_cinhi[i] = hi;
    g_cinlo[i] = __float2bfloat16(v - __bfloat162float(hi));
}

// ---------------- chunk loader (256 threads) ----------------------------------
__device__ __forceinline__ void load_chunk(uint32_t stage, int kc,
    const __nv_bfloat16* Xhi, const __nv_bfloat16* Xlo,
    const __nv_bfloat16* Hhi, const __nv_bfloat16* Hlo,
    const __nv_bfloat16* Wnt, int m0, int t)
{
    const __nv_bfloat16 *phi, *plo; int kb;
    if (kc < 16) { phi = Xhi; plo = Xlo; kb = kc * KC; }
    else         { phi = Hhi; plo = Hlo; kb = (kc-16) * KC; }
    const uint32_t Ahi = stage, Alo = stage + 16384;
    const uint32_t Bhi = stage + 32768, Blo = stage + 49152;
    const int ku = t & 7, rb = t >> 3;          // rb 0..31
    #pragma unroll
    for (int p = 0; p < 4; p++) {
        int row = p*32 + rb;
        int ob  = row*128 + ku*16;
        int swo = ob ^ ((ob >> 3) & 0x70);
        size_t sidx = (size_t)(m0 + row)*FF + kb + ku*8;
        CP16(Ahi + swo, phi + sidx);
        CP16(Alo + swo, plo + sidx);
    }
    const char* wb = (const char*)(Wnt + (size_t)kc*2*8192);
    #pragma unroll
    for (int o = 0; o < 4; o++) {
        int off = o*4096 + t*16;
        CP16(Bhi + off, wb + off);
        CP16(Blo + off, wb + 16384 + off);
    }
}

// ---------------- fused LSTM cell ---------------------------------------------
extern __shared__ char dsm[];

__global__ __launch_bounds__(256, 1)
void lstm_cell(const __nv_bfloat16* __restrict__ Xhi,
               const __nv_bfloat16* __restrict__ Xlo,
               const __nv_bfloat16* __restrict__ Hhi,
               const __nv_bfloat16* __restrict__ Hlo,
               __nv_bfloat16* __restrict__ HWhi,
               __nv_bfloat16* __restrict__ HWlo,
               float* __restrict__ C,
               const __nv_bfloat16* __restrict__ Wlay,
               const float* __restrict__ bih,
               const float* __restrict__ bhh,
               float* __restrict__ out, int out_t)
{
    char* base = (char*)(((uintptr_t)dsm + 1023) & ~(uintptr_t)1023);
    uint32_t sb;
    asm("{ .reg .u64 tmp; cvta.to.shared.u64 tmp, %1; cvt.u32.u64 %0, tmp; }"
        : "=r"(sb) : "l"(base));

    const int t    = threadIdx.x;
    const int w    = t >> 5;
    const int lane = t & 31;
    const int nt   = blockIdx.x;
    const int m0   = blockIdx.y * TM;
    const int f0   = nt * 32;
    float* bias_s  = (float*)(base + OFF_BIAS);

    if (t < 128) {   // bias_s[j]: decode j -> (f, g)
        int u = t >> 4, g = ((t >> 3) & 1)*2 + (t & 1), c = (t >> 1) & 3;
        int f = f0 + 4*u + c;
        bias_s[t] = bih[g*FF + f] + bhh[g*FF + f];
    }
#if USE_TC
    if (w == 0) TCGEN05_ALLOC(sb + OFF_TPTR, 128);
    if (t == 0) {
        #pragma unroll
        for (int s = 0; s < NSTG; s++) MBARRIER_INIT(sb + OFF_MBAR + s*8, 1);
    }
#endif
    __syncthreads();

    const __nv_bfloat16* Wnt = Wlay + (size_t)nt * (32*2*8192);

#if USE_TC
    // ============ tcgen05 path (sm_103a cubin) — deep pipeline =============
    uint32_t tmem = *(uint32_t*)(base + OFF_TPTR);
    int ph[NSTG] = {0, 0, 0};

    // prologue: fill all 3 stages (distance-3 in flight)
    load_chunk(sb + 0*SMEM_STAGE, 0, Xhi, Xlo, Hhi, Hlo, Wnt, m0, t);
    asm volatile("cp.async.commit_group;" ::: "memory");
    load_chunk(sb + 1*SMEM_STAGE, 1, Xhi, Xlo, Hhi, Hlo, Wnt, m0, t);
    asm volatile("cp.async.commit_group;" ::: "memory");
    load_chunk(sb + 2*SMEM_STAGE, 2, Xhi, Xlo, Hhi, Hlo, Wnt, m0, t);
    asm volatile("cp.async.commit_group;" ::: "memory");

    for (int kc = 0; kc < NCH; kc++) {
        const int s = kc % NSTG;

        // refill first: free stage (kc+2)%3 == (kc-1)%3 (needs MMA kc-1 done),
        // issue loads for chunk kc+2, THEN wait for chunk kc's arrival.
        if (kc >= 1 && kc + 2 < NCH) {
            const int sw = (kc - 1) % NSTG;
            MBARRIER_WAIT_PARITY(sb + OFF_MBAR + sw*8, ph[sw]);
            ph[sw] ^= 1;
            load_chunk(sb + sw*SMEM_STAGE, kc + 2, Xhi, Xlo, Hhi, Hlo, Wnt, m0, t);
            asm volatile("cp.async.commit_group;" ::: "memory");
        }

        // tail-aware: allow younger groups to remain in flight
        if (kc + 2 < NCH)      asm volatile("cp.async.wait_group 2;" ::: "memory");
        else if (kc + 1 < NCH) asm volatile("cp.async.wait_group 1;" ::: "memory");
        else                   asm volatile("cp.async.wait_group 0;" ::: "memory");
        __syncthreads();

        if (w == 0) {
            asm volatile("fence.proxy.async.shared::cta;" ::: "memory");
            if (elect_one_pred()) {
                const uint32_t stage = sb + s*SMEM_STAGE;
                uint64_t dah = MAKE_SMEM_DESC(stage);
                uint64_t dal = MAKE_SMEM_DESC(stage + 16384);
                uint64_t dbh = MAKE_SMEM_DESC(stage + 32768);
                uint64_t dbl = MAKE_SMEM_DESC(stage + 49152);
                #pragma unroll
                for (int ks = 0; ks < 4; ks++)      // hi*hi
                    mma_f16_ss(tmem, dah + ks*2, dbh + ks*2, !(kc == 0 && ks == 0));
                #pragma unroll
                for (int ks = 0; ks < 4; ks++)      // hi*lo
                    mma_f16_ss(tmem, dah + ks*2, dbl + ks*2, 1u);
                #pragma unroll
                for (int ks = 0; ks < 4; ks++)      // lo*hi
                    mma_f16_ss(tmem, dal + ks*2, dbh + ks*2, 1u);
                TCGEN05_COMMIT(sb + OFF_MBAR + s*8);
            }
        }
    }

    // drain outstanding MMA commits (chunks NCH-3..NCH-1, distinct mbar slots)
    #pragma unroll
    for (int s = 0; s < NSTG; s++) MBARRIER_WAIT_PARITY(sb + OFF_MBAR + s*8, ph[s]);
    TCGEN05_FENCE_AFTER();

    // epilogue: warp w -> rows (w&3)*32 + lane, parts (w>>2)*2 + {0,1}
    {
        const int m = m0 + (w & 3)*32 + lane;
        float* crow = C + (size_t)m*FF + f0;
        #pragma unroll
        for (int pp = 0; pp < 2; pp++) {
            const int part = (w >> 2)*2 + pp;
            uint32_t d[32];
            TCGEN05_LD_32X32B_X32(d, tmem + part*32);
            TCGEN05_WAIT_LD();
            float4 c0 = *(const float4*)(crow + part*8);
            float4 c1 = *(const float4*)(crow + part*8 + 4);
            float cin[8] = {c0.x, c0.y, c0.z, c0.w, c1.x, c1.y, c1.z, c1.w};
            float cnew[8], hnew[8];
            __nv_bfloat16 hh[8], hl[8];
            #pragma unroll
            for (int fr = 0; fr < 8; fr++) {
                int qb = ((fr >> 2) << 4) + ((fr & 3) << 1);
                float gi = __uint_as_float(d[qb])   + bias_s[part*32 + qb];
                float gf = __uint_as_float(d[qb+1]) + bias_s[part*32 + qb+1];
                float gg = __uint_as_float(d[qb+8]) + bias_s[part*32 + qb+8];
                float go = __uint_as_float(d[qb+9]) + bias_s[part*32 + qb+9];
                float si = 1.0f / (1.0f + __expf(-gi));
                float sf = 1.0f / (1.0f + __expf(-gf));
                float tg = tanhf(gg);
                float so = 1.0f / (1.0f + __expf(-go));
                float cn = sf * cin[fr] + si * tg;
                float hn = so * tanhf(cn);
                cnew[fr] = cn; hnew[fr] = hn;
                __nv_bfloat16 hib = __float2bfloat16(hn);
                hh[fr] = hib;
                hl[fr] = __float2bfloat16(hn - __bfloat162float(hib));
            }
            *(float4*)(crow + part*8)     = make_float4(cnew[0], cnew[1], cnew[2], cnew[3]);
            *(float4*)(crow + part*8 + 4) = make_float4(cnew[4], cnew[5], cnew[6], cnew[7]);
            *(uint4*)(HWhi + (size_t)m*FF + f0 + part*8) = *(const uint4*)hh;
            *(uint4*)(HWlo + (size_t)m*FF + f0 + part*8) = *(const uint4*)hl;
            if (out_t >= 0) {
                #pragma unroll
                for (int fr = 0; fr < 8; fr++)
                    out[((size_t)m*FF + f0 + part*8 + fr)*FUT + out_t] = hnew[fr];
            }
        }
    }
    __syncthreads();
    if (t == 0) {
        #pragma unroll
        for (int s = 0; s < NSTG; s++) MBARRIER_INVAL(sb + OFF_MBAR + s*8);
    }
    __syncthreads();
    if (w == 0) TCGEN05_DEALLOC(tmem, 128);

#else
    // ============ mma.sync HMMA fallback (compute_103 pass) ================
    float acc[2][8][4];
    #pragma unroll
    for (int a = 0; a < 2; a++)
        #pragma unroll
        for (int b = 0; b < 8; b++)
            #pragma unroll
            for (int c = 0; c < 4; c++) acc[a][b][c] = 0.0f;

    const int rbaseA = (w & 3) * 32;
    const int ntb    = (w >> 2) * 8;
    const int a_ro   = (lane & 7) + ((lane >> 3) & 1)*8;
    const int a_bh   = (lane >> 4) * 16;
    const int b_jo   = lane & 7;
    const int b_bh   = ((lane >> 3) & 1) * 16;
    const int b_ts   = lane >> 4;

    load_chunk(sb, 0, Xhi, Xlo, Hhi, Hlo, Wnt, m0, t);
    asm volatile("cp.async.commit_group;" ::: "memory");

    for (int kc = 0; kc < NCH; kc++) {
        if (kc + 1 < NCH) {
            load_chunk(sb + ((kc+1) % NSTG)*SMEM_STAGE, kc + 1,
                       Xhi, Xlo, Hhi, Hlo, Wnt, m0, t);
            asm volatile("cp.async.commit_group;" ::: "memory");
            asm volatile("cp.async.wait_group 1;" ::: "memory");
        } else {
            asm volatile("cp.async.wait_group 0;" ::: "memory");
        }
        __syncthreads();

        const uint32_t stage = sb + (kc % NSTG)*SMEM_STAGE;
        const uint32_t Ahi = stage, Alo = stage + 16384;
        const uint32_t Bhi = stage + 32768, Blo = stage + 49152;

        #pragma unroll
        for (int s16 = 0; s16 < 4; s16++) {
            uint32_t aH[2][4], aL[2][4], bH[8][2], bL[8][2];
            const int abyte = s16*32 + a_bh;
            #pragma unroll
            for (int mt = 0; mt < 2; mt++) {
                int row = rbaseA + mt*16 + a_ro;
                int ob  = row*128 + abyte;
                int swo = ob ^ ((ob >> 3) & 0x70);
                ldsm4(aH[mt][0], aH[mt][1], aH[mt][2], aH[mt][3], Ahi + swo);
                ldsm4(aL[mt][0], aL[mt][1], aL[mt][2], aL[mt][3], Alo + swo);
            }
            const int bbyte = s16*32 + b_bh;
            #pragma unroll
            for (int pp = 0; pp < 4; pp++) {
                int j  = (ntb + 2*pp + b_ts)*8 + b_jo;
                int ob = j*128 + bbyte;
                int swo = ob ^ ((ob >> 3) & 0x70);
                ldsm4(bH[2*pp][0], bH[2*pp][1], bH[2*pp+1][0], bH[2*pp+1][1], Bhi + swo);
                ldsm4(bL[2*pp][0], bL[2*pp][1], bL[2*pp+1][0], bL[2*pp+1][1], Blo + swo);
            }
            #pragma unroll
            for (int mt = 0; mt < 2; mt++)
                #pragma unroll
                for (int nn = 0; nn < 8; nn++) {
                    mma16816(acc[mt][nn], aH[mt], bH[nn]);
                    mma16816(acc[mt][nn], aL[mt], bH[nn]);
                    mma16816(acc[mt][nn], aH[mt], bL[nn]);
                }
        }
        __syncthreads();
    }

    {
        const int c_l = lane & 3;
        const int r_l = lane >> 2;
        #pragma unroll
        for (int mt = 0; mt < 2; mt++)
        #pragma unroll
        for (int ri = 0; ri < 2; ri++) {
            const int m = m0 + rbaseA + mt*16 + ri*8 + r_l;
            #pragma unroll
            for (int up = 0; up < 4; up++) {
                const int u_abs = (w >> 2)*4 + up;
                const int f = f0 + 4*u_abs + c_l;
                const int jb = 16*u_abs + 2*c_l;
                float gi = acc[mt][2*up  ][ri*2    ] + bias_s[jb];
                float gf = acc[mt][2*up  ][ri*2 + 1] + bias_s[jb + 1];
                float gg = acc[mt][2*up+1][ri*2    ] + bias_s[jb + 8];
                float go = acc[mt][2*up+1][ri*2 + 1] + bias_s[jb + 9];
                float si = 1.0f / (1.0f + __expf(-gi));
                float sf = 1.0f / (1.0f + __expf(-gf));
                float tg = tanhf(gg);
                float so = 1.0f / (1.0f + __expf(-go));
                size_t idx = (size_t)m*FF + f;
                float cn = sf * C[idx] + si * tg;
                float hn = so * tanhf(cn);
                C[idx] = cn;
                __nv_bfloat16 hib = __float2bfloat16(hn);
                HWhi[idx] = hib;
                HWlo[idx] = __float2bfloat16(hn - __bfloat162float(hib));
                if (out_t >= 0) out[idx*FUT + out_t] = hn;
            }
        }
    }
#endif
}

// ---------------- host --------------------------------------------------------
extern "C" void kernel_launch(void* const* d_in, const int* in_sizes, int n_in,
                              void* d_out, int out_size)
{
    (void)in_sizes; (void)n_in; (void)out_size;
    const float* seq = (const float*)d_in[0];
    const float* Wih = (const float*)d_in[1];
    const float* Whh = (const float*)d_in[2];
    const float* bih = (const float*)d_in[3];
    const float* bhh = (const float*)d_in[4];
    float* out = (float*)d_out;

    cudaFuncSetAttribute(lstm_cell, cudaFuncAttributeMaxDynamicSharedMemorySize,
                         SMEM_REQ);

    __nv_bfloat16 *pW, *pxhi, *pxlo, *phhi, *phlo, *pcinhi, *pcinlo;
    float *pc;
    cudaGetSymbolAddress((void**)&pW,     g_W);
    cudaGetSymbolAddress((void**)&pxhi,   g_xhi);
    cudaGetSymbolAddress((void**)&pxlo,   g_xlo);
    cudaGetSymbolAddress((void**)&phhi,   g_hhi);
    cudaGetSymbolAddress((void**)&phlo,   g_hlo);
    cudaGetSymbolAddress((void**)&pc,     g_c);
    cudaGetSymbolAddress((void**)&pcinhi, g_cinhi);
    cudaGetSymbolAddress((void**)&pcinlo, g_cinlo);

    const int PLANE = BB*FF;
    {
        long nw = 3L*4096*2048;
        prep_weights<<<(unsigned)((nw + 255)/256), 256>>>(Wih, Whh);
        prep_x<<<(PLANE + 255)/256, 256>>>(seq);
        int nz = 2*NL*PLANE;
        zero_state<<<(nz + 255)/256, 256>>>();
    }

    dim3 grid(FF/32, BB/TM);   // (32, 4) = 128 CTAs
    for (int s = 0; s < HIST + FUT; s++) {
        const int rh = s & 1, wh = rh ^ 1;
        const bool fut = (s >= HIST);
        const int j = s - HIST;
        if (fut && j == 0) prep_cin<<<(PLANE + 255)/256, 256>>>();
        for (int l = 0; l < NL; l++) {
            const __nv_bfloat16 *Xhi, *Xlo;
            if (l > 0)        { Xhi = phhi + (size_t)(wh*NL + (l-1))*PLANE;
                                Xlo = phlo + (size_t)(wh*NL + (l-1))*PLANE; }
            else if (!fut)    { Xhi = pxhi + (size_t)s*PLANE;
                                Xlo = pxlo + (size_t)s*PLANE; }
            else if (j == 0)  { Xhi = pcinhi; Xlo = pcinlo; }
            else              { Xhi = phhi + (size_t)(rh*NL + (NL-1))*PLANE;
                                Xlo = phlo + (size_t)(rh*NL + (NL-1))*PLANE; }
            const __nv_bfloat16* Hhi = phhi + (size_t)(rh*NL + l)*PLANE;
            const __nv_bfloat16* Hlo = phlo + (size_t)(rh*NL + l)*PLANE;
            __nv_bfloat16* HWhi = phhi + (size_t)(wh*NL + l)*PLANE;
            __nv_bfloat16* HWlo = phlo + (size_t)(wh*NL + l)*PLANE;
            float* C = pc + (size_t)l*PLANE;
            const __nv_bfloat16* Wlay = pW + (size_t)l*32*32*2*8192;
            int out_t = (fut && l == NL-1) ? j : -1;
            lstm_cell<<<grid, 256, SMEM_REQ>>>(Xhi, Xlo, Hhi, Hlo, HWhi, HWlo,
                                               C, Wlay,
                                               bih + (size_t)l*4*FF,
                                               bhh + (size_t)l*4*FF,
                                               out, out_t);
        }
    }
}

// round 10
// speedup vs baseline: 3.1800x; 1.2900x over previous
#include <cuda_runtime.h>
#include <cuda_bf16.h>
#include <math.h>
#include <stdint.h>

#define BB   512
#define FF   1024
#define HIST 20
#define FUT  30
#define NL   3

#define TM   128
#define KC   64
#define NCH  32
#define NSTG 3

#define SMEM_STAGE 65536
#define OFF_MBAR   (NSTG*SMEM_STAGE)     // full[3] @ +0, empty[3] @ +24, done @ +48
#define OFF_TPTR   (OFF_MBAR + 56)
#define OFF_BIAS   (OFF_MBAR + 64)
#define SMEM_REQ   (OFF_BIAS + 512 + 1024)

#if defined(__CUDA_ARCH_FEAT_SM103_ALL) || defined(__CUDA_ARCH_FEAT_SM100_ALL)
#define USE_TC 1
#else
#define USE_TC 0
#endif

// idesc kind::f16: dtype=F32, atype=BF16, btype=BF16, N=128, M=128
#define IDESC 0x08200490u

// ---------------- device globals ---------------------------------------------
// EVERYTHING the mainloop streams lives in swizzled 16KB blocks:
//   weights:     g_W  [l][nt][kc][plane][8192]   (as before)
//   activations: [mtile][kc][plane][8192] — A-tile for (mtile, chunk kc) is a
//   contiguous 16KB block per plane, ready for cp.async.bulk.
// Column j = 16u + 8*(g>=2) + 2c + (g&1), f_local = 4u + c.
__device__ __nv_bfloat16 g_W[(size_t)3*32*32*2*8192];
__device__ __nv_bfloat16 g_xC[HIST][4][16][2][8192];
__device__ __nv_bfloat16 g_hC[2][NL][4][16][2][8192];
__device__ __nv_bfloat16 g_cinC[4][16][2][8192];
__device__ float         g_c[NL][BB*FF];

// ---------------- common helpers ---------------------------------------------
#define CP16(dst, src) \
    asm volatile("cp.async.cg.shared.global [%0], [%1], 16;" \
        :: "r"((uint32_t)(dst)), "l"(src) : "memory")

__device__ __forceinline__ void ldsm4(uint32_t& r0, uint32_t& r1,
                                      uint32_t& r2, uint32_t& r3, uint32_t addr) {
    asm volatile("ldmatrix.sync.aligned.m8n8.x4.shared.b16 {%0,%1,%2,%3}, [%4];"
                 : "=r"(r0), "=r"(r1), "=r"(r2), "=r"(r3) : "r"(addr));
}
__device__ __forceinline__ void mma16816(float* c, const uint32_t* a,
                                         const uint32_t* b) {
    asm volatile("mma.sync.aligned.m16n8k16.row.col.f32.bf16.bf16.f32 "
        "{%0,%1,%2,%3}, {%4,%5,%6,%7}, {%8,%9}, {%0,%1,%2,%3};"
        : "+f"(c[0]), "+f"(c[1]), "+f"(c[2]), "+f"(c[3])
        : "r"(a[0]), "r"(a[1]), "r"(a[2]), "r"(a[3]), "r"(b[0]), "r"(b[1]));
}

__device__ __forceinline__ uint32_t elect_one_pred() {
    uint32_t pred;
    asm volatile("{\n\t.reg .pred p;\n\telect.sync _|p, 0xFFFFFFFF;\n\t"
                 "selp.b32 %0, 1, 0, p;\n\t}" : "=r"(pred));
    return pred;
}

#if USE_TC
#define TCGEN05_ALLOC(smem_addr, nCols) \
    asm volatile("tcgen05.alloc.cta_group::1.sync.aligned.shared::cta.b32 [%0], %1;" \
        :: "r"((uint32_t)(smem_addr)), "r"((uint32_t)(nCols)) : "memory")
#define TCGEN05_DEALLOC(tmem_addr, nCols) \
    asm volatile("tcgen05.dealloc.cta_group::1.sync.aligned.b32 %0, %1;" \
        :: "r"(tmem_addr), "r"((uint32_t)(nCols)))
#define TCGEN05_COMMIT(mbar) \
    asm volatile("tcgen05.commit.cta_group::1.mbarrier::arrive::one.shared::cluster.b64 [%0];" \
        :: "r"((uint32_t)(mbar)) : "memory")
#define TCGEN05_FENCE_AFTER() \
    asm volatile("tcgen05.fence::after_thread_sync;" ::: "memory")
#define TCGEN05_WAIT_LD() \
    asm volatile("tcgen05.wait::ld.sync.aligned;" ::: "memory")
#define MBARRIER_INIT(mbar, cnt) \
    asm volatile("mbarrier.init.shared.b64 [%0], %1;" \
        :: "r"((uint32_t)(mbar)), "r"((uint32_t)(cnt)) : "memory")
#define MBARRIER_INVAL(mbar) \
    asm volatile("mbarrier.inval.shared.b64 [%0];" :: "r"((uint32_t)(mbar)) : "memory")
#define MBARRIER_EXPECT_TX(mbar, tx) \
    asm volatile("mbarrier.arrive.expect_tx.shared.b64 _, [%0], %1;" \
        :: "r"((uint32_t)(mbar)), "r"((uint32_t)(tx)) : "memory")
#define MBARRIER_WAIT_PARITY(mbar, parity) do { \
    uint32_t _m = (uint32_t)(mbar); uint32_t _p = (uint32_t)(parity); uint32_t _done; \
    asm volatile("{\n\t.reg .pred p;\n\t" \
        "mbarrier.try_wait.parity.acquire.cta.shared::cta.b64 p, [%1], %2;\n\t" \
        "selp.b32 %0, 1, 0, p;\n\t}" : "=r"(_done) : "r"(_m), "r"(_p) : "memory"); \
    if (!_done) { \
        asm volatile("{\n\t.reg .pred P1;\n\t" \
            "WL_%=:\n\t" \
            "mbarrier.try_wait.parity.acquire.cta.shared::cta.b64 P1, [%0], %1, 0x989680;\n\t" \
            "@P1 bra.uni WD_%=;\n\tbra.uni WL_%=;\n\tWD_%=:\n\t}" \
            :: "r"(_m), "r"(_p) : "memory"); \
    } } while (0)
#define BULK16K(dst, src, mbar) \
    asm volatile("cp.async.bulk.shared::cta.global.mbarrier::complete_tx::bytes " \
        "[%0], [%1], %2, [%3];" \
        :: "r"((uint32_t)(dst)), "l"(src), "r"(16384u), "r"((uint32_t)(mbar)) : "memory")
#define TCGEN05_LD_32X32B_X32(r, tmem_addr) \
    asm volatile("tcgen05.ld.sync.aligned.32x32b.x32.b32 " \
        "{%0, %1, %2, %3, %4, %5, %6, %7, %8, %9, %10, %11, %12, %13, %14, %15, " \
        " %16, %17, %18, %19, %20, %21, %22, %23, %24, %25, %26, %27, %28, %29, %30, %31}, [%32];" \
        : "=r"((r)[0]),  "=r"((r)[1]),  "=r"((r)[2]),  "=r"((r)[3]), \
          "=r"((r)[4]),  "=r"((r)[5]),  "=r"((r)[6]),  "=r"((r)[7]), \
          "=r"((r)[8]),  "=r"((r)[9]),  "=r"((r)[10]), "=r"((r)[11]), \
          "=r"((r)[12]), "=r"((r)[13]), "=r"((r)[14]), "=r"((r)[15]), \
          "=r"((r)[16]), "=r"((r)[17]), "=r"((r)[18]), "=r"((r)[19]), \
          "=r"((r)[20]), "=r"((r)[21]), "=r"((r)[22]), "=r"((r)[23]), \
          "=r"((r)[24]), "=r"((r)[25]), "=r"((r)[26]), "=r"((r)[27]), \
          "=r"((r)[28]), "=r"((r)[29]), "=r"((r)[30]), "=r"((r)[31]) \
        : "r"(tmem_addr))

static constexpr uint64_t SMEM_DESC_BASE_SW128 =
    (uint64_t(2) << 61) | (uint64_t(1) << 46) | (uint64_t(64) << 32) | (uint64_t(1) << 16);
#define MAKE_SMEM_DESC(base_addr) \
    (SMEM_DESC_BASE_SW128 | ((uint64_t)((base_addr) >> 4) & 0x3FFF))

__device__ __forceinline__ void mma_f16_ss(uint32_t d, uint64_t a, uint64_t b,
                                           uint32_t en) {
    asm volatile("{\n\t.reg .pred p;\n\tsetp.ne.u32 p, %5, 0;\n\t"
        "tcgen05.mma.cta_group::1.kind::f16 [%0], %1, %2, %3, {%4,%4,%4,%4}, p;\n\t}"
        :: "r"(d), "l"(a), "l"(b), "r"(IDESC), "r"(0u), "r"(en) : "memory");
}
#endif  // USE_TC

// ---------------- prep kernels -----------------------------------------------
__global__ void prep_weights(const float* __restrict__ Wih,
                             const float* __restrict__ Whh) {
    long i = (long)blockIdx.x * blockDim.x + threadIdx.x;
    if (i >= 3L*4096*2048) return;
    int  k     = (int)(i & 2047);
    long r     = i >> 11;
    int  row_w = (int)(r & 4095);
    int  l     = (int)(r >> 12);
    float w = (k < 1024)
        ? Wih[(long)l*4096*1024 + (long)row_w*1024 + k]
        : Whh[(long)l*4096*1024 + (long)row_w*1024 + (k-1024)];
    __nv_bfloat16 hi = __float2bfloat16(w);
    __nv_bfloat16 lo = __float2bfloat16(w - __bfloat162float(hi));
    int g = row_w >> 10, f = row_w & 1023;
    int nt = f >> 5, fl = f & 31;
    int j = ((fl >> 2) << 4) | ((g >> 1) << 3) | ((fl & 3) << 1) | (g & 1);
    int kc = k >> 6, kl = k & 63;
    int off = j*128 + kl*2;
    off ^= (off >> 3) & 0x70;
    long blk = (((long)l*32 + nt)*32 + kc)*2;
    g_W[(blk + 0)*8192 + (off >> 1)] = hi;
    g_W[(blk + 1)*8192 + (off >> 1)] = lo;
}

__global__ void prep_x(const float* __restrict__ seq) {
    int i = blockIdx.x * blockDim.x + threadIdx.x;   // b*FF + f
    if (i >= BB*FF) return;
    int m = i >> 10, f = i & 1023;
    int mt = m >> 7, row = m & 127, kc = f >> 6, kl = f & 63;
    uint32_t ob = (uint32_t)row*128 + kl*2;
    uint32_t swo = ob ^ ((ob >> 3) & 0x70);
    const float* s = seq + (size_t)i * HIST;
    #pragma unroll
    for (int t = 0; t < HIST; t++) {
        float v = s[t];
        __nv_bfloat16 hi = __float2bfloat16(v);
        g_xC[t][mt][kc][0][swo >> 1] = hi;
        g_xC[t][mt][kc][1][swo >> 1] = __float2bfloat16(v - __bfloat162float(hi));
    }
}

__global__ void zero_state() {
    long i = (long)blockIdx.x * blockDim.x + threadIdx.x;
    const long TH = 2L*NL*4*16*2*8192;
    if (i < TH) ((unsigned short*)g_hC)[i] = 0;
    if (i < (long)NL*BB*FF) ((float*)g_c)[i] = 0.0f;
}

__global__ void prep_cin() {
    int i = blockIdx.x * blockDim.x + threadIdx.x;
    if (i >= BB*FF) return;
    int m = i >> 10, f = i & 1023;
    int mt = m >> 7, row = m & 127, kc = f >> 6, kl = f & 63;
    uint32_t ob = (uint32_t)row*128 + kl*2;
    uint32_t swo = ob ^ ((ob >> 3) & 0x70);
    float v = g_c[NL-1][i];
    __nv_bfloat16 hi = __float2bfloat16(v);
    g_cinC[mt][kc][0][swo >> 1] = hi;
    g_cinC[mt][kc][1][swo >> 1] = __float2bfloat16(v - __bfloat162float(hi));
}

// ---------------- fused LSTM cell ---------------------------------------------
extern __shared__ char dsm[];

__global__ __launch_bounds__(256, 1)
void lstm_cell(const __nv_bfloat16* __restrict__ Xblk,   // [4][16][2][8192]
               const __nv_bfloat16* __restrict__ Hblk,   // recurrent (read)
               __nv_bfloat16* __restrict__ HWblk,        // new h (write)
               float* __restrict__ C,
               const __nv_bfloat16* __restrict__ Wlay,   // [32][32][2][8192]
               const float* __restrict__ bih,
               const float* __restrict__ bhh,
               float* __restrict__ out, int out_t)
{
    char* base = (char*)(((uintptr_t)dsm + 1023) & ~(uintptr_t)1023);
    uint32_t sb;
    asm("{ .reg .u64 tmp; cvta.to.shared.u64 tmp, %1; cvt.u32.u64 %0, tmp; }"
        : "=r"(sb) : "l"(base));

    const int t     = threadIdx.x;
    const int w     = t >> 5;
    const int lane  = t & 31;
    const int nt    = blockIdx.x;
    const int mtile = blockIdx.y;
    const int m0    = mtile * TM;
    const int f0    = nt * 32;
    float* bias_s   = (float*)(base + OFF_BIAS);

    if (t < 128) {   // bias_s[j]: decode j -> (f, g)
        int u = t >> 4, g = ((t >> 3) & 1)*2 + (t & 1), c = (t >> 1) & 3;
        int f = f0 + 4*u + c;
        bias_s[t] = bih[g*FF + f] + bhh[g*FF + f];
    }
#if USE_TC
    if (w == 0) TCGEN05_ALLOC(sb + OFF_TPTR, 128);
    if (t == 0) {
        #pragma unroll
        for (int s = 0; s < NSTG; s++) {
            MBARRIER_INIT(sb + OFF_MBAR + s*8, 1);        // full
            MBARRIER_INIT(sb + OFF_MBAR + 24 + s*8, 1);   // empty
        }
        MBARRIER_INIT(sb + OFF_MBAR + 48, 1);             // done
    }
#endif
    __syncthreads();

    const char* Wnt = (const char*)(Wlay + (size_t)nt * (32*2*8192));
    const char* Xb  = (const char*)Xblk + (size_t)mtile*16*2*16384;
    const char* Hb  = (const char*)Hblk + (size_t)mtile*16*2*16384;

#if USE_TC
    // ===== warp-specialized: w0 = bulk producer, w1 = MMA consumer ==========
    uint32_t tmem = *(uint32_t*)(base + OFF_TPTR);

    if (w == 0) {
        if (elect_one_pred()) {
            for (int kc = 0; kc < NCH; kc++) {
                const int s = kc % NSTG;
                const uint32_t full  = sb + OFF_MBAR + s*8;
                const uint32_t empty = sb + OFF_MBAR + 24 + s*8;
                // empty parity: first use (wrap 0) passes immediately (init phase 1)
                MBARRIER_WAIT_PARITY(empty, 1 ^ ((kc/NSTG) & 1));
                MBARRIER_EXPECT_TX(full, 65536u);
                const char* ab = (kc < 16) ? Xb + (size_t)kc*2*16384
                                           : Hb + (size_t)(kc-16)*2*16384;
                const char* wb = Wnt + (size_t)kc*2*16384;
                const uint32_t st = sb + s*SMEM_STAGE;
                BULK16K(st,         ab,          full);
                BULK16K(st + 16384, ab + 16384,  full);
                BULK16K(st + 32768, wb,          full);
                BULK16K(st + 49152, wb + 16384,  full);
            }
        }
    } else if (w == 1) {
        if (elect_one_pred()) {
            for (int kc = 0; kc < NCH; kc++) {
                const int s = kc % NSTG;
                MBARRIER_WAIT_PARITY(sb + OFF_MBAR + s*8, (kc/NSTG) & 1);
                const uint32_t stage = sb + s*SMEM_STAGE;
                uint64_t dah = MAKE_SMEM_DESC(stage);
                uint64_t dal = MAKE_SMEM_DESC(stage + 16384);
                uint64_t dbh = MAKE_SMEM_DESC(stage + 32768);
                uint64_t dbl = MAKE_SMEM_DESC(stage + 49152);
                #pragma unroll
                for (int ks = 0; ks < 4; ks++)      // hi*hi
                    mma_f16_ss(tmem, dah + ks*2, dbh + ks*2, !(kc == 0 && ks == 0));
                #pragma unroll
                for (int ks = 0; ks < 4; ks++)      // hi*lo
                    mma_f16_ss(tmem, dah + ks*2, dbl + ks*2, 1u);
                #pragma unroll
                for (int ks = 0; ks < 4; ks++)      // lo*hi
                    mma_f16_ss(tmem, dal + ks*2, dbh + ks*2, 1u);
                TCGEN05_COMMIT(sb + OFF_MBAR + 24 + s*8);   // frees stage s
            }
            TCGEN05_COMMIT(sb + OFF_MBAR + 48);             // all MMAs done
        }
    }

    // everyone (incl. producer/consumer lanes) waits for the final commit
    MBARRIER_WAIT_PARITY(sb + OFF_MBAR + 48, 0);
    TCGEN05_FENCE_AFTER();

    // epilogue: warp w -> rows (w&3)*32 + lane, parts (w>>2)*2 + {0,1}
    {
        const int row = (w & 3)*32 + lane;
        const int m = m0 + row;
        float* crow = C + (size_t)m*FF + f0;
        #pragma unroll
        for (int pp = 0; pp < 2; pp++) {
            const int part = (w >> 2)*2 + pp;
            uint32_t d[32];
            TCGEN05_LD_32X32B_X32(d, tmem + part*32);
            TCGEN05_WAIT_LD();
            float4 c0 = *(const float4*)(crow + part*8);
            float4 c1 = *(const float4*)(crow + part*8 + 4);
            float cin[8] = {c0.x, c0.y, c0.z, c0.w, c1.x, c1.y, c1.z, c1.w};
            float cnew[8], hnew[8];
            __nv_bfloat16 hh[8], hl[8];
            #pragma unroll
            for (int fr = 0; fr < 8; fr++) {
                int qb = ((fr >> 2) << 4) + ((fr & 3) << 1);
                float gi = __uint_as_float(d[qb])   + bias_s[part*32 + qb];
                float gf = __uint_as_float(d[qb+1]) + bias_s[part*32 + qb+1];
                float gg = __uint_as_float(d[qb+8]) + bias_s[part*32 + qb+8];
                float go = __uint_as_float(d[qb+9]) + bias_s[part*32 + qb+9];
                float si = 1.0f / (1.0f + __expf(-gi));
                float sf = 1.0f / (1.0f + __expf(-gf));
                float tg = tanhf(gg);
                float so = 1.0f / (1.0f + __expf(-go));
                float cn = sf * cin[fr] + si * tg;
                float hn = so * tanhf(cn);
                cnew[fr] = cn; hnew[fr] = hn;
                __nv_bfloat16 hib = __float2bfloat16(hn);
                hh[fr] = hib;
                hl[fr] = __float2bfloat16(hn - __bfloat162float(hib));
            }
            *(float4*)(crow + part*8)     = make_float4(cnew[0], cnew[1], cnew[2], cnew[3]);
            *(float4*)(crow + part*8 + 4) = make_float4(cnew[4], cnew[5], cnew[6], cnew[7]);
            // write h in chunked swizzled block layout (hi & lo planes)
            {
                int fglob = f0 + part*8;
                int kch = fglob >> 6, kl = fglob & 63;
                uint32_t ob = (uint32_t)row*128 + kl*2;
                uint32_t swo = ob ^ ((ob >> 3) & 0x70);
                char* hb = (char*)HWblk + (size_t)(mtile*16 + kch)*2*16384;
                *(uint4*)(hb + swo)         = *(const uint4*)hh;
                *(uint4*)(hb + 16384 + swo) = *(const uint4*)hl;
            }
            if (out_t >= 0) {
                #pragma unroll
                for (int fr = 0; fr < 8; fr++)
                    out[((size_t)m*FF + f0 + part*8 + fr)*FUT + out_t] = hnew[fr];
            }
        }
    }
    __syncthreads();
    if (t == 0) {
        #pragma unroll
        for (int s = 0; s < NSTG; s++) {
            MBARRIER_INVAL(sb + OFF_MBAR + s*8);
            MBARRIER_INVAL(sb + OFF_MBAR + 24 + s*8);
        }
        MBARRIER_INVAL(sb + OFF_MBAR + 48);
    }
    __syncthreads();
    if (w == 0) TCGEN05_DEALLOC(tmem, 128);

#else
    // ============ mma.sync HMMA fallback (compute_103 pass) ================
    float acc[2][8][4];
    #pragma unroll
    for (int a = 0; a < 2; a++)
        #pragma unroll
        for (int b = 0; b < 8; b++)
            #pragma unroll
            for (int c = 0; c < 4; c++) acc[a][b][c] = 0.0f;

    const int rbaseA = (w & 3) * 32;
    const int ntb    = (w >> 2) * 8;
    const int a_ro   = (lane & 7) + ((lane >> 3) & 1)*8;
    const int a_bh   = (lane >> 4) * 16;
    const int b_jo   = lane & 7;
    const int b_bh   = ((lane >> 3) & 1) * 16;
    const int b_ts   = lane >> 4;

    // per-thread block loader: all four 16KB blocks are contiguous
    auto load_chunk = [&](uint32_t stage, int kc) {
        const char* ab = (kc < 16) ? Xb + (size_t)kc*2*16384
                                   : Hb + (size_t)(kc-16)*2*16384;
        const char* wb = Wnt + (size_t)kc*2*16384;
        #pragma unroll
        for (int p = 0; p < 4; p++) {
            int off = p*4096 + t*16;
            CP16(stage + off,         ab + off);
            CP16(stage + 16384 + off, ab + 16384 + off);
            CP16(stage + 32768 + off, wb + off);
            CP16(stage + 49152 + off, wb + 16384 + off);
        }
    };

    load_chunk(sb, 0);
    asm volatile("cp.async.commit_group;" ::: "memory");

    for (int kc = 0; kc < NCH; kc++) {
        if (kc + 1 < NCH) {
            load_chunk(sb + ((kc+1) % NSTG)*SMEM_STAGE, kc + 1);
            asm volatile("cp.async.commit_group;" ::: "memory");
            asm volatile("cp.async.wait_group 1;" ::: "memory");
        } else {
            asm volatile("cp.async.wait_group 0;" ::: "memory");
        }
        __syncthreads();

        const uint32_t stage = sb + (kc % NSTG)*SMEM_STAGE;
        const uint32_t Ahi = stage, Alo = stage + 16384;
        const uint32_t Bhi = stage + 32768, Blo = stage + 49152;

        #pragma unroll
        for (int s16 = 0; s16 < 4; s16++) {
            uint32_t aH[2][4], aL[2][4], bH[8][2], bL[8][2];
            const int abyte = s16*32 + a_bh;
            #pragma unroll
            for (int mt = 0; mt < 2; mt++) {
                int row = rbaseA + mt*16 + a_ro;
                int ob  = row*128 + abyte;
                int swo = ob ^ ((ob >> 3) & 0x70);
                ldsm4(aH[mt][0], aH[mt][1], aH[mt][2], aH[mt][3], Ahi + swo);
                ldsm4(aL[mt][0], aL[mt][1], aL[mt][2], aL[mt][3], Alo + swo);
            }
            const int bbyte = s16*32 + b_bh;
            #pragma unroll
            for (int pp = 0; pp < 4; pp++) {
                int j  = (ntb + 2*pp + b_ts)*8 + b_jo;
                int ob = j*128 + bbyte;
                int swo = ob ^ ((ob >> 3) & 0x70);
                ldsm4(bH[2*pp][0], bH[2*pp][1], bH[2*pp+1][0], bH[2*pp+1][1], Bhi + swo);
                ldsm4(bL[2*pp][0], bL[2*pp][1], bL[2*pp+1][0], bL[2*pp+1][1], Blo + swo);
            }
            #pragma unroll
            for (int mt = 0; mt < 2; mt++)
                #pragma unroll
                for (int nn = 0; nn < 8; nn++) {
                    mma16816(acc[mt][nn], aH[mt], bH[nn]);
                    mma16816(acc[mt][nn], aL[mt], bH[nn]);
                    mma16816(acc[mt][nn], aH[mt], bL[nn]);
                }
        }
        __syncthreads();
    }

    {
        const int c_l = lane & 3;
        const int r_l = lane >> 2;
        #pragma unroll
        for (int mt = 0; mt < 2; mt++)
        #pragma unroll
        for (int ri = 0; ri < 2; ri++) {
            const int row = rbaseA + mt*16 + ri*8 + r_l;
            const int m = m0 + row;
            #pragma unroll
            for (int up = 0; up < 4; up++) {
                const int u_abs = (w >> 2)*4 + up;
                const int f = f0 + 4*u_abs + c_l;
                const int jb = 16*u_abs + 2*c_l;
                float gi = acc[mt][2*up  ][ri*2    ] + bias_s[jb];
                float gf = acc[mt][2*up  ][ri*2 + 1] + bias_s[jb + 1];
                float gg = acc[mt][2*up+1][ri*2    ] + bias_s[jb + 8];
                float go = acc[mt][2*up+1][ri*2 + 1] + bias_s[jb + 9];
                float si = 1.0f / (1.0f + __expf(-gi));
                float sf = 1.0f / (1.0f + __expf(-gf));
                float tg = tanhf(gg);
                float so = 1.0f / (1.0f + __expf(-go));
                size_t idx = (size_t)m*FF + f;
                float cn = sf * C[idx] + si * tg;
                float hn = so * tanhf(cn);
                C[idx] = cn;
                __nv_bfloat16 hib = __float2bfloat16(hn);
                int kch = f >> 6, kl = f & 63;
                uint32_t ob = (uint32_t)row*128 + kl*2;
                uint32_t swo = ob ^ ((ob >> 3) & 0x70);
                char* hb = (char*)HWblk + (size_t)(mtile*16 + kch)*2*16384;
                *(__nv_bfloat16*)(hb + swo) = hib;
                *(__nv_bfloat16*)(hb + 16384 + swo) =
                    __float2bfloat16(hn - __bfloat162float(hib));
                if (out_t >= 0) out[idx*FUT + out_t] = hn;
            }
        }
    }
#endif
}

// ---------------- host --------------------------------------------------------
extern "C" void kernel_launch(void* const* d_in, const int* in_sizes, int n_in,
                              void* d_out, int out_size)
{
    (void)in_sizes; (void)n_in; (void)out_size;
    const float* seq = (const float*)d_in[0];
    const float* Wih = (const float*)d_in[1];
    const float* Whh = (const float*)d_in[2];
    const float* bih = (const float*)d_in[3];
    const float* bhh = (const float*)d_in[4];
    float* out = (float*)d_out;

    cudaFuncSetAttribute(lstm_cell, cudaFuncAttributeMaxDynamicSharedMemorySize,
                         SMEM_REQ);

    __nv_bfloat16 *pW, *pxC, *phC, *pcinC;
    float *pc;
    cudaGetSymbolAddress((void**)&pW,    g_W);
    cudaGetSymbolAddress((void**)&pxC,   g_xC);
    cudaGetSymbolAddress((void**)&phC,   g_hC);
    cudaGetSymbolAddress((void**)&pcinC, g_cinC);
    cudaGetSymbolAddress((void**)&pc,    g_c);

    const int PLANE = BB*FF;
    const size_t PLANEC = (size_t)4*16*2*8192;   // activation blocks per plane-set

    {
        long nw = 3L*4096*2048;
        prep_weights<<<(unsigned)((nw + 255)/256), 256>>>(Wih, Whh);
        prep_x<<<(PLANE + 255)/256, 256>>>(seq);
        long nz = 2L*NL*4*16*2*8192;
        zero_state<<<(unsigned)((nz + 255)/256), 256>>>();
    }

    dim3 grid(FF/32, BB/TM);   // (32, 4) = 128 CTAs
    for (int s = 0; s < HIST + FUT; s++) {
        const int rh = s & 1, wh = rh ^ 1;
        const bool fut = (s >= HIST);
        const int j = s - HIST;
        if (fut && j == 0) prep_cin<<<(PLANE + 255)/256, 256>>>();
        for (int l = 0; l < NL; l++) {
            const __nv_bfloat16* Xblk;
            if (l > 0)        Xblk = phC + (size_t)(wh*NL + (l-1))*PLANEC;
            else if (!fut)    Xblk = pxC + (size_t)s*PLANEC;
            else if (j == 0)  Xblk = pcinC;
            else              Xblk = phC + (size_t)(rh*NL + (NL-1))*PLANEC;
            const __nv_bfloat16* Hblk = phC + (size_t)(rh*NL + l)*PLANEC;
            __nv_bfloat16* HWblk      = phC + (size_t)(wh*NL + l)*PLANEC;
            float* C = pc + (size_t)l*PLANE;
            const __nv_bfloat16* Wlay = pW + (size_t)l*32*32*2*8192;
            int out_t = (fut && l == NL-1) ? j : -1;
            lstm_cell<<<grid, 256, SMEM_REQ>>>(Xblk, Hblk, HWblk, C, Wlay,
                                               bih + (size_t)l*4*FF,
                                               bhh + (size_t)l*4*FF,
                                               out, out_t);
        }
    }
}